// round 1
// baseline (speedup 1.0000x reference)
#include <cuda_runtime.h>
#include <math.h>

// Problem constants (fixed by the reference)
#define BB 8
#define NN 4096
#define HH 256
#define FF 256

// ---------------------------------------------------------------------------
// Scratch (no cudaMalloc allowed): Q, K activations (fp32), row sums T.
// ---------------------------------------------------------------------------
__device__ float g_Q[BB * NN * FF];   // 32 MB
__device__ float g_K[BB * NN * FF];   // 32 MB
__device__ float g_T[BB * NN];        // 128 KB

__device__ __forceinline__ float sigmoidf_(float x) {
    return 1.0f / (1.0f + __expf(-x));
}

// ---------------------------------------------------------------------------
// Kernel 0: zero T and out (d_out is poisoned before timing)
// ---------------------------------------------------------------------------
__global__ void zero_kernel(float* __restrict__ out) {
    int i = blockIdx.x * blockDim.x + threadIdx.x;
    if (i < BB * NN) g_T[i] = 0.0f;
    if (i < BB * HH) out[i] = 0.0f;
}

// ---------------------------------------------------------------------------
// Kernel 1: Q = sigmoid(h*Wq + bq), K = sigmoid(h*Wk + bk); h = hidden*mask.
// Block = 256 threads (one per output feature f), 16 rows per block.
// ---------------------------------------------------------------------------
#define QK_ROWS 16
__global__ void qk_kernel(const float* __restrict__ hidden,
                          const int*   __restrict__ mask,
                          const float* __restrict__ Wq,
                          const float* __restrict__ bq,
                          const float* __restrict__ Wk,
                          const float* __restrict__ bk) {
    __shared__ float sh[QK_ROWS][HH];
    const int rowBase = blockIdx.x * QK_ROWS;   // row index into [B*N]
    const int f = threadIdx.x;                  // 0..255

    // Load 16 masked hidden rows into smem (coalesced: f contiguous)
    #pragma unroll
    for (int r = 0; r < QK_ROWS; r++) {
        int gr = rowBase + r;
        float m = (float)mask[gr];
        sh[r][f] = hidden[(size_t)gr * HH + f] * m;
    }
    __syncthreads();

    float accQ[QK_ROWS], accK[QK_ROWS];
    const float bqv = bq[f];
    const float bkv = bk[f];
    #pragma unroll
    for (int r = 0; r < QK_ROWS; r++) { accQ[r] = bqv; accK[r] = bkv; }

    #pragma unroll 4
    for (int h = 0; h < HH; h++) {
        float wq = Wq[h * FF + f];   // coalesced across threads
        float wk = Wk[h * FF + f];
        #pragma unroll
        for (int r = 0; r < QK_ROWS; r++) {
            float hv = sh[r][h];     // broadcast
            accQ[r] = fmaf(hv, wq, accQ[r]);
            accK[r] = fmaf(hv, wk, accK[r]);
        }
    }

    #pragma unroll
    for (int r = 0; r < QK_ROWS; r++) {
        int gr = rowBase + r;
        g_Q[(size_t)gr * FF + f] = sigmoidf_(accQ[r]);
        g_K[(size_t)gr * FF + f] = sigmoidf_(accK[r]);
    }
}

// ---------------------------------------------------------------------------
// Kernel 2 (the hotspot): per batch, T[n] += sum_m sigmoid(Q[n]·K[m]) / 16,
// diagonal zeroed. Classic 128x128 SGEMM tile, BK=8, 8x8 per thread,
// fused epilogue (sigmoid + scale + diag-zero + row-sum + atomicAdd).
// ---------------------------------------------------------------------------
#define BM 128
#define BN 128
#define BK 8
__global__ __launch_bounds__(256, 2) void score_kernel() {
    __shared__ float As[BK][BM];
    __shared__ float Bs[BK][BN];
    __shared__ float red[BM][17];   // padded to dodge conflicts

    const int b = blockIdx.z;
    const int rowBase = blockIdx.y * BM;
    const int colBase = blockIdx.x * BN;
    const float* __restrict__ Qb = g_Q + (size_t)b * NN * FF;
    const float* __restrict__ Kb = g_K + (size_t)b * NN * FF;

    const int tid = threadIdx.x;       // 256 threads
    const int tx = tid & 15;           // 0..15 -> 8 cols each
    const int ty = tid >> 4;           // 0..15 -> 8 rows each

    // Global->smem load mapping: thread loads a float4 (half a K-row of 8)
    const int li = tid >> 1;           // 0..127 (tile row)
    const int lk = (tid & 1) * 4;      // 0 or 4

    float acc[8][8];
    #pragma unroll
    for (int i = 0; i < 8; i++)
        #pragma unroll
        for (int j = 0; j < 8; j++) acc[i][j] = 0.0f;

    for (int k0 = 0; k0 < FF; k0 += BK) {
        float4 av = *(const float4*)(Qb + (size_t)(rowBase + li) * FF + k0 + lk);
        float4 bv = *(const float4*)(Kb + (size_t)(colBase + li) * FF + k0 + lk);
        __syncthreads();   // previous iteration's reads done
        As[lk + 0][li] = av.x; As[lk + 1][li] = av.y;
        As[lk + 2][li] = av.z; As[lk + 3][li] = av.w;
        Bs[lk + 0][li] = bv.x; Bs[lk + 1][li] = bv.y;
        Bs[lk + 2][li] = bv.z; Bs[lk + 3][li] = bv.w;
        __syncthreads();

        #pragma unroll
        for (int kk = 0; kk < BK; kk++) {
            float a[8], bb[8];
            *(float4*)(a)      = *(const float4*)&As[kk][ty * 8];
            *(float4*)(a + 4)  = *(const float4*)&As[kk][ty * 8 + 4];
            *(float4*)(bb)     = *(const float4*)&Bs[kk][tx * 8];
            *(float4*)(bb + 4) = *(const float4*)&Bs[kk][tx * 8 + 4];
            #pragma unroll
            for (int i = 0; i < 8; i++)
                #pragma unroll
                for (int j = 0; j < 8; j++)
                    acc[i][j] = fmaf(a[i], bb[j], acc[i][j]);
        }
    }

    // Fused epilogue: sigmoid, 1/sqrt(H) scale, zero diagonal, per-row sum
    const float scale = 0.0625f;   // 1/16
    float rsum[8];
    #pragma unroll
    for (int i = 0; i < 8; i++) {
        const int grow = rowBase + ty * 8 + i;
        float s = 0.0f;
        #pragma unroll
        for (int j = 0; j < 8; j++) {
            const int gcol = colBase + tx * 8 + j;
            float c = sigmoidf_(acc[i][j]) * scale;
            if (grow == gcol) c = 0.0f;
            s += c;
        }
        rsum[i] = s;
    }

    // Reduce the 16 column-thread partials per row, one atomic per row
    #pragma unroll
    for (int i = 0; i < 8; i++) red[ty * 8 + i][tx] = rsum[i];
    __syncthreads();
    if (tid < BM) {
        float s = 0.0f;
        #pragma unroll
        for (int j = 0; j < 16; j++) s += red[tid][j];
        atomicAdd(&g_T[b * NN + rowBase + tid], s);
    }
}

// ---------------------------------------------------------------------------
// Kernel 3: softmax over T rows (in place). One block per batch.
// ---------------------------------------------------------------------------
__global__ void softmax_kernel() {
    __shared__ float sred[256];
    const int b = blockIdx.x;
    const int tid = threadIdx.x;
    float* T = g_T + b * NN;

    float mx = -1e30f;
    for (int n = tid; n < NN; n += 256) mx = fmaxf(mx, T[n]);
    sred[tid] = mx;
    __syncthreads();
    for (int s = 128; s > 0; s >>= 1) {
        if (tid < s) sred[tid] = fmaxf(sred[tid], sred[tid + s]);
        __syncthreads();
    }
    mx = sred[0];
    __syncthreads();

    float sum = 0.0f;
    for (int n = tid; n < NN; n += 256) {
        float e = __expf(T[n] - mx);
        T[n] = e;
        sum += e;
    }
    sred[tid] = sum;
    __syncthreads();
    for (int s = 128; s > 0; s >>= 1) {
        if (tid < s) sred[tid] += sred[tid + s];
        __syncthreads();
    }
    const float inv = 1.0f / sred[0];
    __syncthreads();
    for (int n = tid; n < NN; n += 256) T[n] *= inv;
}

// ---------------------------------------------------------------------------
// Kernel 4: out[b,h] = sum_n t[b,n] * mask[b,n] * hidden[b,n,h]
// Grid (8 segments, B batches); atomicAdd into pre-zeroed out.
// ---------------------------------------------------------------------------
#define SEG 512
__global__ void pool_kernel(const float* __restrict__ hidden,
                            const int*   __restrict__ mask,
                            float* __restrict__ out) {
    __shared__ float t[SEG];
    const int b = blockIdx.y;
    const int n0 = blockIdx.x * SEG;
    const int tid = threadIdx.x;   // 256 = one per h

    for (int n = tid; n < SEG; n += 256) {
        int gn = b * NN + n0 + n;
        t[n] = g_T[gn] * (float)mask[gn];   // fold mask into weight
    }
    __syncthreads();

    float acc = 0.0f;
    const float* hb = hidden + ((size_t)b * NN + n0) * HH + tid;
    #pragma unroll 4
    for (int n = 0; n < SEG; n++)
        acc = fmaf(t[n], hb[(size_t)n * HH], acc);

    atomicAdd(&out[b * HH + tid], acc);
}

// ---------------------------------------------------------------------------
// Launch
// ---------------------------------------------------------------------------
extern "C" void kernel_launch(void* const* d_in, const int* in_sizes, int n_in,
                              void* d_out, int out_size) {
    const float* hidden = (const float*)d_in[0];
    const int*   mask   = (const int*)  d_in[1];
    const float* Wq     = (const float*)d_in[2];
    const float* bq     = (const float*)d_in[3];
    const float* Wk     = (const float*)d_in[4];
    const float* bk     = (const float*)d_in[5];
    float* out = (float*)d_out;

    zero_kernel<<<(BB * NN + 255) / 256, 256>>>(out);

    qk_kernel<<<BB * NN / QK_ROWS, 256>>>(hidden, mask, Wq, bq, Wk, bk);

    dim3 sgrid(NN / BN, NN / BM, BB);   // 32 x 32 x 8
    score_kernel<<<sgrid, 256>>>();

    softmax_kernel<<<BB, 256>>>();

    dim3 pgrid(NN / SEG, BB);           // 8 x 8
    pool_kernel<<<pgrid, 256>>>(hidden, mask, out);
}

// round 2
// speedup vs baseline: 3.8623x; 3.8623x over previous
#include <cuda_runtime.h>
#include <cuda_bf16.h>
#include <math.h>

#define BB 8
#define NN 4096
#define HH 256
#define FF 256

// ---------------------------------------------------------------------------
// Scratch: Q, K activations (bf16), row sums T.
// ---------------------------------------------------------------------------
__device__ __nv_bfloat16 g_Qh[BB * NN * FF];   // 16 MB
__device__ __nv_bfloat16 g_Kh[BB * NN * FF];   // 16 MB
__device__ float g_T[BB * NN];                 // 128 KB

__device__ __forceinline__ float tanh_fast(float x) {
    float y;
    asm("tanh.approx.f32 %0, %1;\n" : "=f"(y) : "f"(x));
    return y;
}
__device__ __forceinline__ float sigmoid_fast(float x) {
    return fmaf(0.5f, tanh_fast(0.5f * x), 0.5f);
}

// ---------------------------------------------------------------------------
// PTX helpers
// ---------------------------------------------------------------------------
__device__ __forceinline__ void ldsm_x4(unsigned& r0, unsigned& r1, unsigned& r2, unsigned& r3,
                                        unsigned addr) {
    asm volatile("ldmatrix.sync.aligned.m8n8.x4.shared.b16 {%0,%1,%2,%3}, [%4];\n"
                 : "=r"(r0), "=r"(r1), "=r"(r2), "=r"(r3) : "r"(addr));
}
__device__ __forceinline__ void mma16816(float* d, const unsigned* a, unsigned b0, unsigned b1) {
    asm volatile(
        "mma.sync.aligned.m16n8k16.row.col.f32.bf16.bf16.f32 "
        "{%0,%1,%2,%3},{%4,%5,%6,%7},{%8,%9},{%0,%1,%2,%3};\n"
        : "+f"(d[0]), "+f"(d[1]), "+f"(d[2]), "+f"(d[3])
        : "r"(a[0]), "r"(a[1]), "r"(a[2]), "r"(a[3]), "r"(b0), "r"(b1));
}
__device__ __forceinline__ void cp_async16(unsigned dst, const void* src) {
    asm volatile("cp.async.cg.shared.global [%0], [%1], 16;\n" :: "r"(dst), "l"(src));
}
#define CP_COMMIT() asm volatile("cp.async.commit_group;\n" ::: "memory")
#define CP_WAIT1()  asm volatile("cp.async.wait_group 1;\n" ::: "memory")

// ---------------------------------------------------------------------------
// Kernel 0: zero T and out
// ---------------------------------------------------------------------------
__global__ void zero_kernel(float* __restrict__ out) {
    int i = blockIdx.x * blockDim.x + threadIdx.x;
    if (i < BB * NN) g_T[i] = 0.0f;
    if (i < BB * HH) out[i] = 0.0f;
}

// ---------------------------------------------------------------------------
// Kernel 1: Q = sigmoid(h*Wq+bq), K = sigmoid(h*Wk+bk), h = hidden*mask.
// Stores bf16. 32 rows per block, 256 threads (one per feature).
// ---------------------------------------------------------------------------
#define QK_ROWS 32
__global__ __launch_bounds__(256) void qk_kernel(const float* __restrict__ hidden,
                          const int*   __restrict__ mask,
                          const float* __restrict__ Wq,
                          const float* __restrict__ bq,
                          const float* __restrict__ Wk,
                          const float* __restrict__ bk) {
    __shared__ float sh[QK_ROWS][HH];
    const int rowBase = blockIdx.x * QK_ROWS;
    const int f = threadIdx.x;

    #pragma unroll
    for (int r = 0; r < QK_ROWS; r++) {
        int gr = rowBase + r;
        float m = (float)mask[gr];
        sh[r][f] = hidden[(size_t)gr * HH + f] * m;
    }
    __syncthreads();

    float accQ[QK_ROWS], accK[QK_ROWS];
    const float bqv = bq[f];
    const float bkv = bk[f];
    #pragma unroll
    for (int r = 0; r < QK_ROWS; r++) { accQ[r] = bqv; accK[r] = bkv; }

    #pragma unroll 2
    for (int h = 0; h < HH; h++) {
        float wq = Wq[h * FF + f];
        float wk = Wk[h * FF + f];
        #pragma unroll
        for (int r = 0; r < QK_ROWS; r++) {
            float hv = sh[r][h];
            accQ[r] = fmaf(hv, wq, accQ[r]);
            accK[r] = fmaf(hv, wk, accK[r]);
        }
    }

    #pragma unroll
    for (int r = 0; r < QK_ROWS; r++) {
        int gr = rowBase + r;
        g_Qh[(size_t)gr * FF + f] = __float2bfloat16(sigmoid_fast(accQ[r]));
        g_Kh[(size_t)gr * FF + f] = __float2bfloat16(sigmoid_fast(accK[r]));
    }
}

// ---------------------------------------------------------------------------
// Kernel 2: tensor-core score kernel.
// Per batch: T[n] += sum_m sigmoid(Q[n]·K[m])/16, diag zeroed.
// BM=BN=128, BK=64 bf16, 8 warps, mma.m16n8k16, SW128 swizzle, cp.async x2.
// ---------------------------------------------------------------------------
#define BM 128
#define BN 128
#define BKS 64          // bf16 per K-step (128 bytes per row)
#define STAGE_BYTES 32768   // A(16KB) + B(16KB)

__device__ __forceinline__ float sig_scaled(float x) {
    // sigmoid(x) / 16, exploiting fp32 saturation for x > 16
    if (x > 16.0f) return 0.0625f;
    return 0.0625f / (1.0f + __expf(-x));
}

extern __shared__ char s_score[];

__global__ __launch_bounds__(256, 2) void score_kernel() {
    const int b = blockIdx.z;
    const int rowBase = blockIdx.y * BM;
    const int colBase = blockIdx.x * BN;
    const __nv_bfloat16* __restrict__ Qb = g_Qh + (size_t)b * NN * FF;
    const __nv_bfloat16* __restrict__ Kb = g_Kh + (size_t)b * NN * FF;

    const int tid = threadIdx.x;
    const int wid = tid >> 5;
    const int lane = tid & 31;
    const int wr = wid >> 1;     // 0..3 : 32-row stripe
    const int wc = wid & 1;      // 0..1 : 64-col stripe

    unsigned sbase = (unsigned)__cvta_generic_to_shared(s_score);

    float acc[2][8][4];
    #pragma unroll
    for (int mi = 0; mi < 2; mi++)
        #pragma unroll
        for (int nf = 0; nf < 8; nf++)
            #pragma unroll
            for (int q = 0; q < 4; q++) acc[mi][nf][q] = 0.0f;

    // ---- tile loader (cp.async, SW128 swizzle) ----
    auto load_tile = [&](int stage, int k0) {
        unsigned Ab = sbase + stage * STAGE_BYTES;
        unsigned Bb = Ab + 16384;
        #pragma unroll
        for (int i = 0; i < 4; i++) {
            int idx = tid + i * 256;         // 0..1023
            int r  = idx >> 3;               // 0..127
            int cb = idx & 7;                // 16B chunk
            unsigned off = r * 128 + ((cb ^ (r & 7)) << 4);
            cp_async16(Ab + off, Qb + (size_t)(rowBase + r) * FF + k0 + cb * 8);
            cp_async16(Bb + off, Kb + (size_t)(colBase + r) * FF + k0 + cb * 8);
        }
    };

    load_tile(0, 0);
    CP_COMMIT();

    const int NSTEP = FF / BKS;   // 4
    for (int ks = 0; ks < NSTEP; ks++) {
        if (ks + 1 < NSTEP) load_tile((ks + 1) & 1, (ks + 1) * BKS);
        CP_COMMIT();
        CP_WAIT1();
        __syncthreads();

        unsigned Ab = sbase + (ks & 1) * STAGE_BYTES;
        unsigned Bb = Ab + 16384;

        #pragma unroll
        for (int kk = 0; kk < 4; kk++) {      // 4 k16 steps per BK=64
            unsigned a[2][4];
            #pragma unroll
            for (int mi = 0; mi < 2; mi++) {
                int r = wr * 32 + mi * 16 + (lane & 15);
                int ch = kk * 2 + (lane >> 4);
                ldsm_x4(a[mi][0], a[mi][1], a[mi][2], a[mi][3],
                        Ab + r * 128 + ((ch ^ (r & 7)) << 4));
            }
            unsigned bv[4][4];
            #pragma unroll
            for (int nb = 0; nb < 4; nb++) {
                int n = wc * 64 + nb * 16 + (lane & 7) + ((lane >> 4) << 3);
                int ch = kk * 2 + ((lane >> 3) & 1);
                ldsm_x4(bv[nb][0], bv[nb][1], bv[nb][2], bv[nb][3],
                        Bb + n * 128 + ((ch ^ (n & 7)) << 4));
            }
            #pragma unroll
            for (int mi = 0; mi < 2; mi++)
                #pragma unroll
                for (int nf = 0; nf < 8; nf++)
                    mma16816(acc[mi][nf], a[mi],
                             bv[nf >> 1][(nf & 1) * 2], bv[nf >> 1][(nf & 1) * 2 + 1]);
        }
        __syncthreads();
    }

    // ---- fused epilogue: saturating sigmoid, diag-zero, row sums ----
    float* red = (float*)s_score;   // reuse stage-0 A area (free after last compute)

    #pragma unroll
    for (int mi = 0; mi < 2; mi++) {
        int lrow_lo = wr * 32 + mi * 16 + (lane >> 2);
        int lrow_hi = lrow_lo + 8;
        int grow_lo = rowBase + lrow_lo;
        int grow_hi = rowBase + lrow_hi;
        float slo = 0.0f, shi = 0.0f;
        #pragma unroll
        for (int nf = 0; nf < 8; nf++) {
            int col0 = colBase + wc * 64 + nf * 8 + 2 * (lane & 3);
            int col1 = col0 + 1;
            float v;
            v = sig_scaled(acc[mi][nf][0]); if (grow_lo != col0) slo += v;
            v = sig_scaled(acc[mi][nf][1]); if (grow_lo != col1) slo += v;
            v = sig_scaled(acc[mi][nf][2]); if (grow_hi != col0) shi += v;
            v = sig_scaled(acc[mi][nf][3]); if (grow_hi != col1) shi += v;
        }
        // reduce across the 4 lanes sharing a row
        slo += __shfl_xor_sync(0xffffffff, slo, 1);
        slo += __shfl_xor_sync(0xffffffff, slo, 2);
        shi += __shfl_xor_sync(0xffffffff, shi, 1);
        shi += __shfl_xor_sync(0xffffffff, shi, 2);
        if ((lane & 3) == 0) {
            red[(lrow_lo << 1) | wc] = slo;
            red[(lrow_hi << 1) | wc] = shi;
        }
    }
    __syncthreads();
    if (tid < BM) {
        atomicAdd(&g_T[b * NN + rowBase + tid], red[tid * 2] + red[tid * 2 + 1]);
    }
}

// ---------------------------------------------------------------------------
// Kernel 3: softmax over T rows (in place). One block per batch.
// ---------------------------------------------------------------------------
__global__ void softmax_kernel() {
    __shared__ float sred[256];
    const int b = blockIdx.x;
    const int tid = threadIdx.x;
    float* T = g_T + b * NN;

    float mx = -1e30f;
    for (int n = tid; n < NN; n += 256) mx = fmaxf(mx, T[n]);
    sred[tid] = mx;
    __syncthreads();
    for (int s = 128; s > 0; s >>= 1) {
        if (tid < s) sred[tid] = fmaxf(sred[tid], sred[tid + s]);
        __syncthreads();
    }
    mx = sred[0];
    __syncthreads();

    float sum = 0.0f;
    for (int n = tid; n < NN; n += 256) {
        float e = __expf(T[n] - mx);
        T[n] = e;
        sum += e;
    }
    sred[tid] = sum;
    __syncthreads();
    for (int s = 128; s > 0; s >>= 1) {
        if (tid < s) sred[tid] += sred[tid + s];
        __syncthreads();
    }
    const float inv = 1.0f / sred[0];
    __syncthreads();
    for (int n = tid; n < NN; n += 256) T[n] *= inv;
}

// ---------------------------------------------------------------------------
// Kernel 4: out[b,h] = sum_n t[b,n] * mask[b,n] * hidden[b,n,h]
// ---------------------------------------------------------------------------
#define SEG 512
__global__ void pool_kernel(const float* __restrict__ hidden,
                            const int*   __restrict__ mask,
                            float* __restrict__ out) {
    __shared__ float t[SEG];
    const int b = blockIdx.y;
    const int n0 = blockIdx.x * SEG;
    const int tid = threadIdx.x;

    for (int n = tid; n < SEG; n += 256) {
        int gn = b * NN + n0 + n;
        t[n] = g_T[gn] * (float)mask[gn];
    }
    __syncthreads();

    float acc = 0.0f;
    const float* hb = hidden + ((size_t)b * NN + n0) * HH + tid;
    #pragma unroll 4
    for (int n = 0; n < SEG; n++)
        acc = fmaf(t[n], hb[(size_t)n * HH], acc);

    atomicAdd(&out[b * HH + tid], acc);
}

// ---------------------------------------------------------------------------
// Launch
// ---------------------------------------------------------------------------
extern "C" void kernel_launch(void* const* d_in, const int* in_sizes, int n_in,
                              void* d_out, int out_size) {
    const float* hidden = (const float*)d_in[0];
    const int*   mask   = (const int*)  d_in[1];
    const float* Wq     = (const float*)d_in[2];
    const float* bq     = (const float*)d_in[3];
    const float* Wk     = (const float*)d_in[4];
    const float* bk     = (const float*)d_in[5];
    float* out = (float*)d_out;

    cudaFuncSetAttribute(score_kernel,
                         cudaFuncAttributeMaxDynamicSharedMemorySize, 2 * STAGE_BYTES);

    zero_kernel<<<(BB * NN + 255) / 256, 256>>>(out);

    qk_kernel<<<BB * NN / QK_ROWS, 256>>>(hidden, mask, Wq, bq, Wk, bk);

    dim3 sgrid(NN / BN, NN / BM, BB);
    score_kernel<<<sgrid, 256, 2 * STAGE_BYTES>>>();

    softmax_kernel<<<BB, 256>>>();

    dim3 pgrid(NN / SEG, BB);
    pool_kernel<<<pgrid, 256>>>(hidden, mask, out);
}

// round 4
// speedup vs baseline: 16.6066x; 4.2997x over previous
#include <cuda_runtime.h>
#include <cuda_bf16.h>
#include <math.h>
#include <cstdint>

#define BB 8
#define NN 4096
#define HH 256
#define FF 256

// ---------------------------------------------------------------------------
// Scratch
// ---------------------------------------------------------------------------
__device__ __nv_bfloat16 g_Qh[BB * NN * FF];   // 16 MB
__device__ __nv_bfloat16 g_Kh[BB * NN * FF];   // 16 MB
__device__ float g_T[BB * NN];                 // 128 KB
__device__ __nv_bfloat16 g_WT[512 * HH];       // combined [Wq^T ; Wk^T], [f, h]
__device__ float g_b2[512];                    // combined bias
__device__ float g_Sq[BB * NN], g_Aq[BB * NN]; // row sum, centered sq-norm (Q)
__device__ float g_Sk[BB * NN], g_Ak[BB * NN]; // same for K
__device__ int   g_flag[BB];                   // 1 => all scores saturate

__device__ __forceinline__ float tanh_fast(float x) {
    float y;
    asm("tanh.approx.f32 %0, %1;\n" : "=f"(y) : "f"(x));
    return y;
}
__device__ __forceinline__ float sigmoid_fast(float x) {
    return fmaf(0.5f, tanh_fast(0.5f * x), 0.5f);
}

// ---------------------------------------------------------------------------
// PTX helpers (legacy mma.sync path only — tcgen05 unavailable in this build)
// ---------------------------------------------------------------------------
__device__ __forceinline__ void ldsm_x4(unsigned& r0, unsigned& r1, unsigned& r2, unsigned& r3,
                                        unsigned addr) {
    asm volatile("ldmatrix.sync.aligned.m8n8.x4.shared.b16 {%0,%1,%2,%3}, [%4];\n"
                 : "=r"(r0), "=r"(r1), "=r"(r2), "=r"(r3) : "r"(addr));
}
__device__ __forceinline__ void mma16816(float* d, const unsigned* a, unsigned b0, unsigned b1) {
    asm volatile(
        "mma.sync.aligned.m16n8k16.row.col.f32.bf16.bf16.f32 "
        "{%0,%1,%2,%3},{%4,%5,%6,%7},{%8,%9},{%0,%1,%2,%3};\n"
        : "+f"(d[0]), "+f"(d[1]), "+f"(d[2]), "+f"(d[3])
        : "r"(a[0]), "r"(a[1]), "r"(a[2]), "r"(a[3]), "r"(b0), "r"(b1));
}
__device__ __forceinline__ void cp_async16(unsigned dst, const void* src) {
    asm volatile("cp.async.cg.shared.global [%0], [%1], 16;\n" :: "r"(dst), "l"(src));
}
#define CP_COMMIT() asm volatile("cp.async.commit_group;\n" ::: "memory")
#define CP_WAIT1()  asm volatile("cp.async.wait_group 1;\n" ::: "memory")
#define CP_WAIT0()  asm volatile("cp.async.wait_group 0;\n" ::: "memory")

// ---------------------------------------------------------------------------
// Kernel 0: zero T and out
// ---------------------------------------------------------------------------
__global__ void zero_kernel(float* __restrict__ out) {
    int i = blockIdx.x * blockDim.x + threadIdx.x;
    if (i < BB * NN) g_T[i] = 0.0f;
    if (i < BB * HH) out[i] = 0.0f;
}

// ---------------------------------------------------------------------------
// Kernel W: build combined transposed bf16 weights WT[f,h] and bias
// ---------------------------------------------------------------------------
__global__ void wt_prep_kernel(const float* __restrict__ Wq, const float* __restrict__ bq,
                               const float* __restrict__ Wk, const float* __restrict__ bk) {
    int f = blockIdx.x;          // 0..511
    int h = threadIdx.x;         // 0..255
    float w = (f < FF) ? Wq[h * FF + f] : Wk[h * FF + (f - FF)];
    g_WT[f * HH + h] = __float2bfloat16(w);
    if (h == 0) g_b2[f] = (f < FF) ? bq[f] : bk[f - FF];
}

// ---------------------------------------------------------------------------
// Kernel 1: tensor-core QK projection.
// C[row, f(0..511)] = sigmoid( (hidden*mask)[row,:] . WT[f,:] + b2[f] )
// A: 128 rows x 256 k bf16 resident in smem (converted fp32->bf16, mask folded).
// B: 128-f tiles, k-chunks of 64 streamed via cp.async (2 stages).
// ---------------------------------------------------------------------------
#define QA_BYTES 65536                 // 128 x 256 bf16 (4 chunk-blocks of 16KB)
#define QB_STAGE 16384                 // 128 x 64 bf16
#define QBIAS_OFF (QA_BYTES + 2 * QB_STAGE)
#define QK_SMEM (QBIAS_OFF + 512 * 4)

extern __shared__ char s_qk[];

__global__ __launch_bounds__(256, 2) void qk_tc_kernel(const float* __restrict__ hidden,
                                                       const int* __restrict__ mask) {
    const int rowBase = blockIdx.x * 128;
    const int tid = threadIdx.x;
    const int wid = tid >> 5;
    const int lane = tid & 31;
    const int wr = wid >> 1;     // 0..3 : 32-row stripe
    const int wc = wid & 1;      // 0..1 : 64-col stripe
    const uint32_t sb = (uint32_t)__cvta_generic_to_shared(s_qk);
    const uint32_t Asm = sb;
    const uint32_t Bsm = sb + QA_BYTES;
    float* sBias = (float*)(s_qk + QBIAS_OFF);

    sBias[tid] = g_b2[tid];
    sBias[tid + 256] = g_b2[tid + 256];

    // ---- load A: hidden*mask -> bf16, swizzled, chunk-blocked (c*16KB) ----
    #pragma unroll
    for (int c = 0; c < 4; c++) {
        #pragma unroll
        for (int i = 0; i < 4; i++) {
            int idx = tid + i * 256;       // 0..1023
            int r = idx >> 3;              // 0..127
            int cb = idx & 7;              // 8-bf16 unit within 64-k chunk
            const float* src = hidden + (size_t)(rowBase + r) * HH + c * 64 + cb * 8;
            float m = (float)mask[rowBase + r];
            float4 f0 = *(const float4*)src;
            float4 f1 = *(const float4*)(src + 4);
            __nv_bfloat162 p0 = __floats2bfloat162_rn(f0.x * m, f0.y * m);
            __nv_bfloat162 p1 = __floats2bfloat162_rn(f0.z * m, f0.w * m);
            __nv_bfloat162 p2 = __floats2bfloat162_rn(f1.x * m, f1.y * m);
            __nv_bfloat162 p3 = __floats2bfloat162_rn(f1.z * m, f1.w * m);
            uint32_t dst = Asm + c * 16384 + r * 128 + ((cb ^ (r & 7)) << 4);
            asm volatile("st.shared.v4.b32 [%0], {%1,%2,%3,%4};\n"
                         :: "r"(dst),
                            "r"(*(uint32_t*)&p0), "r"(*(uint32_t*)&p1),
                            "r"(*(uint32_t*)&p2), "r"(*(uint32_t*)&p3) : "memory");
        }
    }
    __syncthreads();

    // ---- 4 f-tiles of 128 combined output features ----
    for (int ft = 0; ft < 4; ft++) {
        auto loadB = [&](int stage, int c) {
            #pragma unroll
            for (int i = 0; i < 2; i++) {
                int idx = tid + i * 256;   // 0..511
                int r = idx >> 3;          // 0..127 (feature row)
                int cb = idx & 7;
                cp_async16(Bsm + stage * QB_STAGE + r * 128 + ((cb ^ (r & 7)) << 4),
                           g_WT + (size_t)(ft * 128 + r) * HH + c * 64 + cb * 8);
            }
        };

        float acc[2][8][4];
        #pragma unroll
        for (int mi = 0; mi < 2; mi++)
            #pragma unroll
            for (int nf = 0; nf < 8; nf++)
                #pragma unroll
                for (int q = 0; q < 4; q++) acc[mi][nf][q] = 0.0f;

        loadB(0, 0); CP_COMMIT();
        loadB(1, 1); CP_COMMIT();

        #pragma unroll
        for (int c = 0; c < 4; c++) {
            if (c < 3) { CP_WAIT1(); } else { CP_WAIT0(); }
            __syncthreads();

            uint32_t Ab = Asm + c * 16384;
            uint32_t Bb = Bsm + (c & 1) * QB_STAGE;

            #pragma unroll
            for (int kk = 0; kk < 4; kk++) {
                unsigned a[2][4];
                #pragma unroll
                for (int mi = 0; mi < 2; mi++) {
                    int r = wr * 32 + mi * 16 + (lane & 15);
                    int ch = kk * 2 + (lane >> 4);
                    ldsm_x4(a[mi][0], a[mi][1], a[mi][2], a[mi][3],
                            Ab + r * 128 + ((ch ^ (r & 7)) << 4));
                }
                unsigned bv[4][4];
                #pragma unroll
                for (int nb = 0; nb < 4; nb++) {
                    int n = wc * 64 + nb * 16 + (lane & 7) + ((lane >> 4) << 3);
                    int ch = kk * 2 + ((lane >> 3) & 1);
                    ldsm_x4(bv[nb][0], bv[nb][1], bv[nb][2], bv[nb][3],
                            Bb + n * 128 + ((ch ^ (n & 7)) << 4));
                }
                #pragma unroll
                for (int mi = 0; mi < 2; mi++)
                    #pragma unroll
                    for (int nf = 0; nf < 8; nf++)
                        mma16816(acc[mi][nf], a[mi],
                                 bv[nf >> 1][(nf & 1) * 2], bv[nf >> 1][(nf & 1) * 2 + 1]);
            }
            __syncthreads();
            if (c < 2) { loadB(c & 1, c + 2); CP_COMMIT(); }
        }

        // ---- epilogue: bias + sigmoid, store bf16x2 into Qh/Kh ----
        #pragma unroll
        for (int mi = 0; mi < 2; mi++) {
            int row_lo = rowBase + wr * 32 + mi * 16 + (lane >> 2);
            int row_hi = row_lo + 8;
            #pragma unroll
            for (int nf = 0; nf < 8; nf++) {
                int col = ft * 128 + wc * 64 + nf * 8 + 2 * (lane & 3);
                float b0 = sBias[col], b1 = sBias[col + 1];
                float v00 = sigmoid_fast(acc[mi][nf][0] + b0);
                float v01 = sigmoid_fast(acc[mi][nf][1] + b1);
                float v10 = sigmoid_fast(acc[mi][nf][2] + b0);
                float v11 = sigmoid_fast(acc[mi][nf][3] + b1);
                __nv_bfloat162 plo = __floats2bfloat162_rn(v00, v01);
                __nv_bfloat162 phi = __floats2bfloat162_rn(v10, v11);
                if (col < FF) {
                    *(uint32_t*)&g_Qh[(size_t)row_lo * FF + col] = *(uint32_t*)&plo;
                    *(uint32_t*)&g_Qh[(size_t)row_hi * FF + col] = *(uint32_t*)&phi;
                } else {
                    *(uint32_t*)&g_Kh[(size_t)row_lo * FF + col - FF] = *(uint32_t*)&plo;
                    *(uint32_t*)&g_Kh[(size_t)row_hi * FF + col - FF] = *(uint32_t*)&phi;
                }
            }
        }
    }
}

// ---------------------------------------------------------------------------
// Kernel S: per-row stats. S = sum(q), A = sum((q-0.5)^2). One warp per row.
// ---------------------------------------------------------------------------
__global__ __launch_bounds__(256) void stats_kernel() {
    const int row = blockIdx.x * 8 + (threadIdx.x >> 5);
    const int lane = threadIdx.x & 31;

    const __nv_bfloat16* q = g_Qh + (size_t)row * FF;
    const __nv_bfloat16* k = g_Kh + (size_t)row * FF;
    float sq = 0.0f, aq = 0.0f, sk = 0.0f, ak = 0.0f;
    #pragma unroll
    for (int j = 0; j < 8; j++) {
        float vq = __bfloat162float(q[lane + j * 32]);
        float vk = __bfloat162float(k[lane + j * 32]);
        sq += vq; aq += (vq - 0.5f) * (vq - 0.5f);
        sk += vk; ak += (vk - 0.5f) * (vk - 0.5f);
    }
    #pragma unroll
    for (int o = 16; o > 0; o >>= 1) {
        sq += __shfl_xor_sync(0xffffffff, sq, o);
        aq += __shfl_xor_sync(0xffffffff, aq, o);
        sk += __shfl_xor_sync(0xffffffff, sk, o);
        ak += __shfl_xor_sync(0xffffffff, ak, o);
    }
    if (lane == 0) {
        g_Sq[row] = sq; g_Aq[row] = aq;
        g_Sk[row] = sk; g_Ak[row] = ak;
    }
}

// ---------------------------------------------------------------------------
// Kernel G: per-batch saturation proof.
// dot(Qn,Km) >= 64 + 0.5(minSq-128) + 0.5(minSk-128) - sqrt(maxAq)*sqrt(maxAk)
// If bound > 18, every off-diag sigmoid == 1.0f exactly -> T constant.
// ---------------------------------------------------------------------------
__global__ __launch_bounds__(256) void guard_kernel() {
    __shared__ float smn[256], smx[256], smn2[256], smx2[256];
    const int b = blockIdx.x;
    const int tid = threadIdx.x;
    float mnSq = 1e30f, mxAq = 0.0f, mnSk = 1e30f, mxAk = 0.0f;
    for (int n = tid; n < NN; n += 256) {
        int i = b * NN + n;
        mnSq = fminf(mnSq, g_Sq[i]); mxAq = fmaxf(mxAq, g_Aq[i]);
        mnSk = fminf(mnSk, g_Sk[i]); mxAk = fmaxf(mxAk, g_Ak[i]);
    }
    smn[tid] = mnSq; smx[tid] = mxAq; smn2[tid] = mnSk; smx2[tid] = mxAk;
    __syncthreads();
    for (int s = 128; s > 0; s >>= 1) {
        if (tid < s) {
            smn[tid] = fminf(smn[tid], smn[tid + s]);
            smx[tid] = fmaxf(smx[tid], smx[tid + s]);
            smn2[tid] = fminf(smn2[tid], smn2[tid + s]);
            smx2[tid] = fmaxf(smx2[tid], smx2[tid + s]);
        }
        __syncthreads();
    }
    if (tid == 0) {
        float bound = 64.0f + 0.5f * (smn[0] - 128.0f) + 0.5f * (smn2[0] - 128.0f)
                    - sqrtf(smx[0]) * sqrtf(smx2[0]);
        g_flag[b] = (bound > 18.0f) ? 1 : 0;
    }
}

// ---------------------------------------------------------------------------
// Kernel 2 (fallback): mma.sync score kernel with per-batch early exit.
// Only runs if the saturation proof fails for that batch.
// ---------------------------------------------------------------------------
#define SBM 128
#define SBN 128
#define S_STAGE_BYTES 32768

__device__ __forceinline__ float sig_scaled(float x) {
    if (x > 16.0f) return 0.0625f;
    return 0.0625f / (1.0f + __expf(-x));
}

extern __shared__ char s_score[];

__global__ __launch_bounds__(256, 2) void score_kernel() {
    const int b = blockIdx.z;
    if (g_flag[b]) return;   // saturation proven: T constant -> handled by softmax(0)

    const int rowBase = blockIdx.y * SBM;
    const int colBase = blockIdx.x * SBN;
    const __nv_bfloat16* __restrict__ Qb = g_Qh + (size_t)b * NN * FF;
    const __nv_bfloat16* __restrict__ Kb = g_Kh + (size_t)b * NN * FF;

    const int tid = threadIdx.x;
    const int wid = tid >> 5;
    const int lane = tid & 31;
    const int wr = wid >> 1;
    const int wc = wid & 1;

    unsigned sbase = (unsigned)__cvta_generic_to_shared(s_score);

    float acc[2][8][4];
    #pragma unroll
    for (int mi = 0; mi < 2; mi++)
        #pragma unroll
        for (int nf = 0; nf < 8; nf++)
            #pragma unroll
            for (int q = 0; q < 4; q++) acc[mi][nf][q] = 0.0f;

    auto load_tile = [&](int stage, int k0) {
        unsigned Ab = sbase + stage * S_STAGE_BYTES;
        unsigned Bb = Ab + 16384;
        #pragma unroll
        for (int i = 0; i < 4; i++) {
            int idx = tid + i * 256;
            int r = idx >> 3;
            int cb = idx & 7;
            unsigned off = r * 128 + ((cb ^ (r & 7)) << 4);
            cp_async16(Ab + off, Qb + (size_t)(rowBase + r) * FF + k0 + cb * 8);
            cp_async16(Bb + off, Kb + (size_t)(colBase + r) * FF + k0 + cb * 8);
        }
    };

    load_tile(0, 0);
    CP_COMMIT();

    const int NSTEP = FF / 64;
    for (int ks = 0; ks < NSTEP; ks++) {
        if (ks + 1 < NSTEP) load_tile((ks + 1) & 1, (ks + 1) * 64);
        CP_COMMIT();
        CP_WAIT1();
        __syncthreads();

        unsigned Ab = sbase + (ks & 1) * S_STAGE_BYTES;
        unsigned Bb = Ab + 16384;

        #pragma unroll
        for (int kk = 0; kk < 4; kk++) {
            unsigned a[2][4];
            #pragma unroll
            for (int mi = 0; mi < 2; mi++) {
                int r = wr * 32 + mi * 16 + (lane & 15);
                int ch = kk * 2 + (lane >> 4);
                ldsm_x4(a[mi][0], a[mi][1], a[mi][2], a[mi][3],
                        Ab + r * 128 + ((ch ^ (r & 7)) << 4));
            }
            unsigned bv[4][4];
            #pragma unroll
            for (int nb = 0; nb < 4; nb++) {
                int n = wc * 64 + nb * 16 + (lane & 7) + ((lane >> 4) << 3);
                int ch = kk * 2 + ((lane >> 3) & 1);
                ldsm_x4(bv[nb][0], bv[nb][1], bv[nb][2], bv[nb][3],
                        Bb + n * 128 + ((ch ^ (n & 7)) << 4));
            }
            #pragma unroll
            for (int mi = 0; mi < 2; mi++)
                #pragma unroll
                for (int nf = 0; nf < 8; nf++)
                    mma16816(acc[mi][nf], a[mi],
                             bv[nf >> 1][(nf & 1) * 2], bv[nf >> 1][(nf & 1) * 2 + 1]);
        }
        __syncthreads();
    }

    float* red = (float*)s_score;

    #pragma unroll
    for (int mi = 0; mi < 2; mi++) {
        int lrow_lo = wr * 32 + mi * 16 + (lane >> 2);
        int lrow_hi = lrow_lo + 8;
        int grow_lo = rowBase + lrow_lo;
        int grow_hi = rowBase + lrow_hi;
        float slo = 0.0f, shi = 0.0f;
        #pragma unroll
        for (int nf = 0; nf < 8; nf++) {
            int col0 = colBase + wc * 64 + nf * 8 + 2 * (lane & 3);
            int col1 = col0 + 1;
            float v;
            v = sig_scaled(acc[mi][nf][0]); if (grow_lo != col0) slo += v;
            v = sig_scaled(acc[mi][nf][1]); if (grow_lo != col1) slo += v;
            v = sig_scaled(acc[mi][nf][2]); if (grow_hi != col0) shi += v;
            v = sig_scaled(acc[mi][nf][3]); if (grow_hi != col1) shi += v;
        }
        slo += __shfl_xor_sync(0xffffffff, slo, 1);
        slo += __shfl_xor_sync(0xffffffff, slo, 2);
        shi += __shfl_xor_sync(0xffffffff, shi, 1);
        shi += __shfl_xor_sync(0xffffffff, shi, 2);
        if ((lane & 3) == 0) {
            red[(lrow_lo << 1) | wc] = slo;
            red[(lrow_hi << 1) | wc] = shi;
        }
    }
    __syncthreads();
    if (tid < SBM) {
        atomicAdd(&g_T[b * NN + rowBase + tid], red[tid * 2] + red[tid * 2 + 1]);
    }
}

// ---------------------------------------------------------------------------
// Kernel 3: softmax over T rows (T==0 => exact uniform 1/N, matching the
// reference's constant-T case bit-for-bit since 1/4096 is a power of two).
// ---------------------------------------------------------------------------
__global__ void softmax_kernel() {
    __shared__ float sred[256];
    const int b = blockIdx.x;
    const int tid = threadIdx.x;
    float* T = g_T + b * NN;

    float mx = -1e30f;
    for (int n = tid; n < NN; n += 256) mx = fmaxf(mx, T[n]);
    sred[tid] = mx;
    __syncthreads();
    for (int s = 128; s > 0; s >>= 1) {
        if (tid < s) sred[tid] = fmaxf(sred[tid], sred[tid + s]);
        __syncthreads();
    }
    mx = sred[0];
    __syncthreads();

    float sum = 0.0f;
    for (int n = tid; n < NN; n += 256) {
        float e = __expf(T[n] - mx);
        T[n] = e;
        sum += e;
    }
    sred[tid] = sum;
    __syncthreads();
    for (int s = 128; s > 0; s >>= 1) {
        if (tid < s) sred[tid] += sred[tid + s];
        __syncthreads();
    }
    const float inv = 1.0f / sred[0];
    __syncthreads();
    for (int n = tid; n < NN; n += 256) T[n] *= inv;
}

// ---------------------------------------------------------------------------
// Kernel 4: out[b,h] = sum_n t[b,n] * mask[b,n] * hidden[b,n,h]
// ---------------------------------------------------------------------------
#define SEG 512
__global__ void pool_kernel(const float* __restrict__ hidden,
                            const int*   __restrict__ mask,
                            float* __restrict__ out) {
    __shared__ float t[SEG];
    const int b = blockIdx.y;
    const int n0 = blockIdx.x * SEG;
    const int tid = threadIdx.x;

    for (int n = tid; n < SEG; n += 256) {
        int gn = b * NN + n0 + n;
        t[n] = g_T[gn] * (float)mask[gn];
    }
    __syncthreads();

    float acc = 0.0f;
    const float* hb = hidden + ((size_t)b * NN + n0) * HH + tid;
    #pragma unroll 4
    for (int n = 0; n < SEG; n++)
        acc = fmaf(t[n], hb[(size_t)n * HH], acc);

    atomicAdd(&out[b * HH + tid], acc);
}

// ---------------------------------------------------------------------------
// Launch
// ---------------------------------------------------------------------------
extern "C" void kernel_launch(void* const* d_in, const int* in_sizes, int n_in,
                              void* d_out, int out_size) {
    const float* hidden = (const float*)d_in[0];
    const int*   mask   = (const int*)  d_in[1];
    const float* Wq     = (const float*)d_in[2];
    const float* bq     = (const float*)d_in[3];
    const float* Wk     = (const float*)d_in[4];
    const float* bk     = (const float*)d_in[5];
    float* out = (float*)d_out;

    cudaFuncSetAttribute(qk_tc_kernel,
                         cudaFuncAttributeMaxDynamicSharedMemorySize, QK_SMEM);
    cudaFuncSetAttribute(score_kernel,
                         cudaFuncAttributeMaxDynamicSharedMemorySize, 2 * S_STAGE_BYTES);

    zero_kernel<<<(BB * NN + 255) / 256, 256>>>(out);

    wt_prep_kernel<<<512, 256>>>(Wq, bq, Wk, bk);

    qk_tc_kernel<<<BB * NN / 128, 256, QK_SMEM>>>(hidden, mask);

    stats_kernel<<<BB * NN / 8, 256>>>();
    guard_kernel<<<BB, 256>>>();

    dim3 sgrid(NN / SBN, NN / SBM, BB);   // fallback; early-exits when proven
    score_kernel<<<sgrid, 256, 2 * S_STAGE_BYTES>>>();

    softmax_kernel<<<BB, 256>>>();

    dim3 pgrid(NN / SEG, BB);
    pool_kernel<<<pgrid, 256>>>(hidden, mask, out);
}

// round 6
// speedup vs baseline: 25.9640x; 1.5635x over previous
#include <cuda_runtime.h>
#include <cuda_bf16.h>
#include <math.h>
#include <cstdint>

#define BB 8
#define NN 4096
#define HH 256
#define FF 256

// ---------------------------------------------------------------------------
// Scratch
// ---------------------------------------------------------------------------
__device__ __nv_bfloat16 g_Qh[BB * NN * FF];   // 16 MB
__device__ __nv_bfloat16 g_Kh[BB * NN * FF];   // 16 MB
__device__ float g_T[BB * NN];                 // 128 KB
__device__ __nv_bfloat16 g_WT[512 * HH];       // combined [Wq^T ; Wk^T], [f, h]
__device__ float g_b2[512];                    // combined bias
__device__ float g_Sq[BB * NN], g_Aq[BB * NN]; // row sum, centered sq-norm (Q)
__device__ float g_Sk[BB * NN], g_Ak[BB * NN]; // same for K
__device__ int   g_flag[BB];                   // 1 => all scores saturate

__device__ __forceinline__ float tanh_fast(float x) {
    float y;
    asm("tanh.approx.f32 %0, %1;\n" : "=f"(y) : "f"(x));
    return y;
}
__device__ __forceinline__ float sigmoid_fast(float x) {
    return fmaf(0.5f, tanh_fast(0.5f * x), 0.5f);
}

// ---------------------------------------------------------------------------
// PTX helpers (legacy mma.sync path — tcgen05 unavailable in this toolchain)
// ---------------------------------------------------------------------------
__device__ __forceinline__ void ldsm_x4(unsigned& r0, unsigned& r1, unsigned& r2, unsigned& r3,
                                        unsigned addr) {
    asm volatile("ldmatrix.sync.aligned.m8n8.x4.shared.b16 {%0,%1,%2,%3}, [%4];\n"
                 : "=r"(r0), "=r"(r1), "=r"(r2), "=r"(r3) : "r"(addr));
}
__device__ __forceinline__ void mma16816(float* d, const unsigned* a, unsigned b0, unsigned b1) {
    asm volatile(
        "mma.sync.aligned.m16n8k16.row.col.f32.bf16.bf16.f32 "
        "{%0,%1,%2,%3},{%4,%5,%6,%7},{%8,%9},{%0,%1,%2,%3};\n"
        : "+f"(d[0]), "+f"(d[1]), "+f"(d[2]), "+f"(d[3])
        : "r"(a[0]), "r"(a[1]), "r"(a[2]), "r"(a[3]), "r"(b0), "r"(b1));
}
__device__ __forceinline__ void cp_async16(unsigned dst, const void* src) {
    asm volatile("cp.async.cg.shared.global [%0], [%1], 16;\n" :: "r"(dst), "l"(src));
}
#define CP_COMMIT() asm volatile("cp.async.commit_group;\n" ::: "memory")
#define CP_WAIT1()  asm volatile("cp.async.wait_group 1;\n" ::: "memory")
#define CP_WAIT0()  asm volatile("cp.async.wait_group 0;\n" ::: "memory")

// ---------------------------------------------------------------------------
// Kernel 0: zero T, stats, out
// ---------------------------------------------------------------------------
__global__ void zero_kernel(float* __restrict__ out) {
    int i = blockIdx.x * blockDim.x + threadIdx.x;
    if (i < BB * NN) {
        g_T[i] = 0.0f;
    }
    if (i < BB * HH) out[i] = 0.0f;
}

// ---------------------------------------------------------------------------
// Kernel W: build combined transposed bf16 weights WT[f,h] and bias
// ---------------------------------------------------------------------------
__global__ void wt_prep_kernel(const float* __restrict__ Wq, const float* __restrict__ bq,
                               const float* __restrict__ Wk, const float* __restrict__ bk) {
    int f = blockIdx.x;          // 0..511
    int h = threadIdx.x;         // 0..255
    float w = (f < FF) ? Wq[h * FF + f] : Wk[h * FF + (f - FF)];
    g_WT[f * HH + h] = __float2bfloat16(w);
    if (h == 0) g_b2[f] = (f < FF) ? bq[f] : bk[f - FF];
}

// ---------------------------------------------------------------------------
// Kernel 1: tensor-core QK projection (verified round-4 version, unchanged).
// C[row, f(0..511)] = sigmoid( (hidden*mask)[row,:] . WT[f,:] + b2[f] )
// ---------------------------------------------------------------------------
#define QA_BYTES 65536                 // 128 x 256 bf16 (4 chunk-blocks of 16KB)
#define QB_STAGE 16384                 // 128 x 64 bf16
#define QBIAS_OFF (QA_BYTES + 2 * QB_STAGE)
#define QK_SMEM (QBIAS_OFF + 512 * 4)

extern __shared__ char s_qk[];

__global__ __launch_bounds__(256, 2) void qk_tc_kernel(const float* __restrict__ hidden,
                                                       const int* __restrict__ mask) {
    const int rowBase = blockIdx.x * 128;
    const int tid = threadIdx.x;
    const int wid = tid >> 5;
    const int lane = tid & 31;
    const int wr = wid >> 1;     // 0..3 : 32-row stripe
    const int wc = wid & 1;      // 0..1 : 64-col stripe
    const uint32_t sb = (uint32_t)__cvta_generic_to_shared(s_qk);
    const uint32_t Asm = sb;
    const uint32_t Bsm = sb + QA_BYTES;
    float* sBias = (float*)(s_qk + QBIAS_OFF);

    sBias[tid] = g_b2[tid];
    sBias[tid + 256] = g_b2[tid + 256];

    // ---- load A: hidden*mask -> bf16, swizzled, chunk-blocked ----
    #pragma unroll
    for (int c = 0; c < 4; c++) {
        #pragma unroll
        for (int i = 0; i < 4; i++) {
            int idx = tid + i * 256;
            int r = idx >> 3;
            int cb = idx & 7;
            const float* src = hidden + (size_t)(rowBase + r) * HH + c * 64 + cb * 8;
            float m = (float)mask[rowBase + r];
            float4 f0 = *(const float4*)src;
            float4 f1 = *(const float4*)(src + 4);
            __nv_bfloat162 p0 = __floats2bfloat162_rn(f0.x * m, f0.y * m);
            __nv_bfloat162 p1 = __floats2bfloat162_rn(f0.z * m, f0.w * m);
            __nv_bfloat162 p2 = __floats2bfloat162_rn(f1.x * m, f1.y * m);
            __nv_bfloat162 p3 = __floats2bfloat162_rn(f1.z * m, f1.w * m);
            uint32_t dst = Asm + c * 16384 + r * 128 + ((cb ^ (r & 7)) << 4);
            asm volatile("st.shared.v4.b32 [%0], {%1,%2,%3,%4};\n"
                         :: "r"(dst),
                            "r"(*(uint32_t*)&p0), "r"(*(uint32_t*)&p1),
                            "r"(*(uint32_t*)&p2), "r"(*(uint32_t*)&p3) : "memory");
        }
    }
    __syncthreads();

    // ---- 4 f-tiles of 128 combined output features ----
    for (int ft = 0; ft < 4; ft++) {
        auto loadB = [&](int stage, int c) {
            #pragma unroll
            for (int i = 0; i < 2; i++) {
                int idx = tid + i * 256;
                int r = idx >> 3;
                int cb = idx & 7;
                cp_async16(Bsm + stage * QB_STAGE + r * 128 + ((cb ^ (r & 7)) << 4),
                           g_WT + (size_t)(ft * 128 + r) * HH + c * 64 + cb * 8);
            }
        };

        float acc[2][8][4];
        #pragma unroll
        for (int mi = 0; mi < 2; mi++)
            #pragma unroll
            for (int nf = 0; nf < 8; nf++)
                #pragma unroll
                for (int q = 0; q < 4; q++) acc[mi][nf][q] = 0.0f;

        loadB(0, 0); CP_COMMIT();
        loadB(1, 1); CP_COMMIT();

        #pragma unroll
        for (int c = 0; c < 4; c++) {
            if (c < 3) { CP_WAIT1(); } else { CP_WAIT0(); }
            __syncthreads();

            uint32_t Ab = Asm + c * 16384;
            uint32_t Bb = Bsm + (c & 1) * QB_STAGE;

            #pragma unroll
            for (int kk = 0; kk < 4; kk++) {
                unsigned a[2][4];
                #pragma unroll
                for (int mi = 0; mi < 2; mi++) {
                    int r = wr * 32 + mi * 16 + (lane & 15);
                    int ch = kk * 2 + (lane >> 4);
                    ldsm_x4(a[mi][0], a[mi][1], a[mi][2], a[mi][3],
                            Ab + r * 128 + ((ch ^ (r & 7)) << 4));
                }
                unsigned bv[4][4];
                #pragma unroll
                for (int nb = 0; nb < 4; nb++) {
                    int n = wc * 64 + nb * 16 + (lane & 7) + ((lane >> 4) << 3);
                    int ch = kk * 2 + ((lane >> 3) & 1);
                    ldsm_x4(bv[nb][0], bv[nb][1], bv[nb][2], bv[nb][3],
                            Bb + n * 128 + ((ch ^ (n & 7)) << 4));
                }
                #pragma unroll
                for (int mi = 0; mi < 2; mi++)
                    #pragma unroll
                    for (int nf = 0; nf < 8; nf++)
                        mma16816(acc[mi][nf], a[mi],
                                 bv[nf >> 1][(nf & 1) * 2], bv[nf >> 1][(nf & 1) * 2 + 1]);
            }
            __syncthreads();
            if (c < 2) { loadB(c & 1, c + 2); CP_COMMIT(); }
        }

        // ---- epilogue: bias + sigmoid, store bf16x2 into Qh/Kh ----
        #pragma unroll
        for (int mi = 0; mi < 2; mi++) {
            int row_lo = rowBase + wr * 32 + mi * 16 + (lane >> 2);
            int row_hi = row_lo + 8;
            #pragma unroll
            for (int nf = 0; nf < 8; nf++) {
                int col = ft * 128 + wc * 64 + nf * 8 + 2 * (lane & 3);
                float b0 = sBias[col], b1 = sBias[col + 1];
                float v00 = sigmoid_fast(acc[mi][nf][0] + b0);
                float v01 = sigmoid_fast(acc[mi][nf][1] + b1);
                float v10 = sigmoid_fast(acc[mi][nf][2] + b0);
                float v11 = sigmoid_fast(acc[mi][nf][3] + b1);
                __nv_bfloat162 plo = __floats2bfloat162_rn(v00, v01);
                __nv_bfloat162 phi = __floats2bfloat162_rn(v10, v11);
                if (col < FF) {
                    *(uint32_t*)&g_Qh[(size_t)row_lo * FF + col] = *(uint32_t*)&plo;
                    *(uint32_t*)&g_Qh[(size_t)row_hi * FF + col] = *(uint32_t*)&phi;
                } else {
                    *(uint32_t*)&g_Kh[(size_t)row_lo * FF + col - FF] = *(uint32_t*)&plo;
                    *(uint32_t*)&g_Kh[(size_t)row_hi * FF + col - FF] = *(uint32_t*)&phi;
                }
            }
        }
    }
}

// ---------------------------------------------------------------------------
// Kernel S: per-row stats, vectorized. One warp per row; one uint4 per lane
// (8 bf16). S = sum(v), A = sum((v-0.5)^2). Direct stores (no atomics).
// ---------------------------------------------------------------------------
__global__ __launch_bounds__(256) void stats_kernel() {
    const int row = blockIdx.x * 8 + (threadIdx.x >> 5);
    const int lane = threadIdx.x & 31;

    const uint4* qv = (const uint4*)(g_Qh + (size_t)row * FF);
    const uint4* kv = (const uint4*)(g_Kh + (size_t)row * FF);
    uint4 q = qv[lane];    // 8 bf16
    uint4 k = kv[lane];

    float sq = 0.0f, aq = 0.0f, sk = 0.0f, ak = 0.0f;
    uint32_t qw[4] = {q.x, q.y, q.z, q.w};
    uint32_t kw[4] = {k.x, k.y, k.z, k.w};
    #pragma unroll
    for (int j = 0; j < 4; j++) {
        __nv_bfloat162 pq = *(__nv_bfloat162*)&qw[j];
        __nv_bfloat162 pk = *(__nv_bfloat162*)&kw[j];
        float q0 = __low2float(pq), q1 = __high2float(pq);
        float k0 = __low2float(pk), k1 = __high2float(pk);
        sq += q0 + q1;
        aq += (q0 - 0.5f) * (q0 - 0.5f) + (q1 - 0.5f) * (q1 - 0.5f);
        sk += k0 + k1;
        ak += (k0 - 0.5f) * (k0 - 0.5f) + (k1 - 0.5f) * (k1 - 0.5f);
    }
    #pragma unroll
    for (int o = 16; o > 0; o >>= 1) {
        sq += __shfl_xor_sync(0xffffffff, sq, o);
        aq += __shfl_xor_sync(0xffffffff, aq, o);
        sk += __shfl_xor_sync(0xffffffff, sk, o);
        ak += __shfl_xor_sync(0xffffffff, ak, o);
    }
    if (lane == 0) {
        g_Sq[row] = sq; g_Aq[row] = aq;
        g_Sk[row] = sk; g_Ak[row] = ak;
    }
}

// ---------------------------------------------------------------------------
// Kernel G: per-batch saturation proof.
// dot(Qn,Km) >= 64 + 0.5(minSq-128) + 0.5(minSk-128) - sqrt(maxAq*maxAk) > 18
// => every off-diag sigmoid == 1.0f exactly (fp32 saturates at ~17.5).
// ---------------------------------------------------------------------------
__global__ __launch_bounds__(256) void guard_kernel() {
    __shared__ float smn[256], smx[256], smn2[256], smx2[256];
    const int b = blockIdx.x;
    const int tid = threadIdx.x;
    float mnSq = 1e30f, mxAq = 0.0f, mnSk = 1e30f, mxAk = 0.0f;
    for (int n = tid; n < NN; n += 256) {
        int i = b * NN + n;
        mnSq = fminf(mnSq, g_Sq[i]); mxAq = fmaxf(mxAq, g_Aq[i]);
        mnSk = fminf(mnSk, g_Sk[i]); mxAk = fmaxf(mxAk, g_Ak[i]);
    }
    smn[tid] = mnSq; smx[tid] = mxAq; smn2[tid] = mnSk; smx2[tid] = mxAk;
    __syncthreads();
    for (int s = 128; s > 0; s >>= 1) {
        if (tid < s) {
            smn[tid] = fminf(smn[tid], smn[tid + s]);
            smx[tid] = fmaxf(smx[tid], smx[tid + s]);
            smn2[tid] = fminf(smn2[tid], smn2[tid + s]);
            smx2[tid] = fmaxf(smx2[tid], smx2[tid + s]);
        }
        __syncthreads();
    }
    if (tid == 0) {
        float bound = 64.0f + 0.5f * (smn[0] - 128.0f) + 0.5f * (smn2[0] - 128.0f)
                    - sqrtf(smx[0]) * sqrtf(smx2[0]);
        g_flag[b] = (bound > 18.0f) ? 1 : 0;
    }
}

// ---------------------------------------------------------------------------
// Kernel 2 (fallback): mma.sync score kernel; early-exits if saturation proven.
// ---------------------------------------------------------------------------
#define SBM 128
#define SBN 128
#define S_STAGE_BYTES 32768

__device__ __forceinline__ float sig_scaled(float x) {
    if (x > 16.0f) return 0.0625f;
    return 0.0625f / (1.0f + __expf(-x));
}

extern __shared__ char s_score[];

__global__ __launch_bounds__(256, 2) void score_kernel() {
    const int b = blockIdx.z;
    if (g_flag[b]) return;

    const int rowBase = blockIdx.y * SBM;
    const int colBase = blockIdx.x * SBN;
    const __nv_bfloat16* __restrict__ Qb = g_Qh + (size_t)b * NN * FF;
    const __nv_bfloat16* __restrict__ Kb = g_Kh + (size_t)b * NN * FF;

    const int tid = threadIdx.x;
    const int wid = tid >> 5;
    const int lane = tid & 31;
    const int wr = wid >> 1;
    const int wc = wid & 1;

    unsigned sbase = (unsigned)__cvta_generic_to_shared(s_score);

    float acc[2][8][4];
    #pragma unroll
    for (int mi = 0; mi < 2; mi++)
        #pragma unroll
        for (int nf = 0; nf < 8; nf++)
            #pragma unroll
            for (int q = 0; q < 4; q++) acc[mi][nf][q] = 0.0f;

    auto load_tile = [&](int stage, int k0) {
        unsigned Ab = sbase + stage * S_STAGE_BYTES;
        unsigned Bb = Ab + 16384;
        #pragma unroll
        for (int i = 0; i < 4; i++) {
            int idx = tid + i * 256;
            int r = idx >> 3;
            int cb = idx & 7;
            unsigned off = r * 128 + ((cb ^ (r & 7)) << 4);
            cp_async16(Ab + off, Qb + (size_t)(rowBase + r) * FF + k0 + cb * 8);
            cp_async16(Bb + off, Kb + (size_t)(colBase + r) * FF + k0 + cb * 8);
        }
    };

    load_tile(0, 0);
    CP_COMMIT();

    const int NSTEP = FF / 64;
    for (int ks = 0; ks < NSTEP; ks++) {
        if (ks + 1 < NSTEP) load_tile((ks + 1) & 1, (ks + 1) * 64);
        CP_COMMIT();
        CP_WAIT1();
        __syncthreads();

        unsigned Ab = sbase + (ks & 1) * S_STAGE_BYTES;
        unsigned Bb = Ab + 16384;

        #pragma unroll
        for (int kk = 0; kk < 4; kk++) {
            unsigned a[2][4];
            #pragma unroll
            for (int mi = 0; mi < 2; mi++) {
                int r = wr * 32 + mi * 16 + (lane & 15);
                int ch = kk * 2 + (lane >> 4);
                ldsm_x4(a[mi][0], a[mi][1], a[mi][2], a[mi][3],
                        Ab + r * 128 + ((ch ^ (r & 7)) << 4));
            }
            unsigned bv[4][4];
            #pragma unroll
            for (int nb = 0; nb < 4; nb++) {
                int n = wc * 64 + nb * 16 + (lane & 7) + ((lane >> 4) << 3);
                int ch = kk * 2 + ((lane >> 3) & 1);
                ldsm_x4(bv[nb][0], bv[nb][1], bv[nb][2], bv[nb][3],
                        Bb + n * 128 + ((ch ^ (n & 7)) << 4));
            }
            #pragma unroll
            for (int mi = 0; mi < 2; mi++)
                #pragma unroll
                for (int nf = 0; nf < 8; nf++)
                    mma16816(acc[mi][nf], a[mi],
                             bv[nf >> 1][(nf & 1) * 2], bv[nf >> 1][(nf & 1) * 2 + 1]);
        }
        __syncthreads();
    }

    float* red = (float*)s_score;

    #pragma unroll
    for (int mi = 0; mi < 2; mi++) {
        int lrow_lo = wr * 32 + mi * 16 + (lane >> 2);
        int lrow_hi = lrow_lo + 8;
        int grow_lo = rowBase + lrow_lo;
        int grow_hi = rowBase + lrow_hi;
        float slo = 0.0f, shi = 0.0f;
        #pragma unroll
        for (int nf = 0; nf < 8; nf++) {
            int col0 = colBase + wc * 64 + nf * 8 + 2 * (lane & 3);
            int col1 = col0 + 1;
            float v;
            v = sig_scaled(acc[mi][nf][0]); if (grow_lo != col0) slo += v;
            v = sig_scaled(acc[mi][nf][1]); if (grow_lo != col1) slo += v;
            v = sig_scaled(acc[mi][nf][2]); if (grow_hi != col0) shi += v;
            v = sig_scaled(acc[mi][nf][3]); if (grow_hi != col1) shi += v;
        }
        slo += __shfl_xor_sync(0xffffffff, slo, 1);
        slo += __shfl_xor_sync(0xffffffff, slo, 2);
        shi += __shfl_xor_sync(0xffffffff, shi, 1);
        shi += __shfl_xor_sync(0xffffffff, shi, 2);
        if ((lane & 3) == 0) {
            red[(lrow_lo << 1) | wc] = slo;
            red[(lrow_hi << 1) | wc] = shi;
        }
    }
    __syncthreads();
    if (tid < SBM) {
        atomicAdd(&g_T[b * NN + rowBase + tid], red[tid * 2] + red[tid * 2 + 1]);
    }
}

// ---------------------------------------------------------------------------
// Kernel 3: softmax over T rows. Skipped for proven-saturated batches
// (pool then uses the exact uniform weight 1/4096 = softmax of constant T).
// ---------------------------------------------------------------------------
__global__ void softmax_kernel() {
    __shared__ float sred[256];
    const int b = blockIdx.x;
    if (g_flag[b]) return;
    const int tid = threadIdx.x;
    float* T = g_T + b * NN;

    float mx = -1e30f;
    for (int n = tid; n < NN; n += 256) mx = fmaxf(mx, T[n]);
    sred[tid] = mx;
    __syncthreads();
    for (int s = 128; s > 0; s >>= 1) {
        if (tid < s) sred[tid] = fmaxf(sred[tid], sred[tid + s]);
        __syncthreads();
    }
    mx = sred[0];
    __syncthreads();

    float sum = 0.0f;
    for (int n = tid; n < NN; n += 256) {
        float e = __expf(T[n] - mx);
        T[n] = e;
        sum += e;
    }
    sred[tid] = sum;
    __syncthreads();
    for (int s = 128; s > 0; s >>= 1) {
        if (tid < s) sred[tid] += sred[tid + s];
        __syncthreads();
    }
    const float inv = 1.0f / sred[0];
    __syncthreads();
    for (int n = tid; n < NN; n += 256) T[n] *= inv;
}

// ---------------------------------------------------------------------------
// Kernel 4: out[b,h] = sum_n w[b,n] * mask[b,n] * hidden[b,n,h]
// w = 1/4096 exactly (saturated case) or softmaxed T (fallback case).
// ---------------------------------------------------------------------------
#define PSEG 128
__global__ __launch_bounds__(256) void pool_kernel(const float* __restrict__ hidden,
                            const int*   __restrict__ mask,
                            float* __restrict__ out) {
    __shared__ float t[PSEG];
    const int b = blockIdx.y;
    const int n0 = blockIdx.x * PSEG;
    const int tid = threadIdx.x;
    const int flag = g_flag[b];

    if (tid < PSEG) {
        int gn = b * NN + n0 + tid;
        float w = flag ? 2.44140625e-4f : g_T[gn];   // 1/4096 exact
        t[tid] = w * (float)mask[gn];
    }
    __syncthreads();

    float acc = 0.0f;
    const float* hb = hidden + ((size_t)b * NN + n0) * HH + tid;
    #pragma unroll 8
    for (int n = 0; n < PSEG; n++)
        acc = fmaf(t[n], hb[(size_t)n * HH], acc);

    atomicAdd(&out[b * HH + tid], acc);
}

// ---------------------------------------------------------------------------
// Launch
// ---------------------------------------------------------------------------
extern "C" void kernel_launch(void* const* d_in, const int* in_sizes, int n_in,
                              void* d_out, int out_size) {
    const float* hidden = (const float*)d_in[0];
    const int*   mask   = (const int*)  d_in[1];
    const float* Wq     = (const float*)d_in[2];
    const float* bq     = (const float*)d_in[3];
    const float* Wk     = (const float*)d_in[4];
    const float* bk     = (const float*)d_in[5];
    float* out = (float*)d_out;

    cudaFuncSetAttribute(qk_tc_kernel,
                         cudaFuncAttributeMaxDynamicSharedMemorySize, QK_SMEM);
    cudaFuncSetAttribute(score_kernel,
                         cudaFuncAttributeMaxDynamicSharedMemorySize, 2 * S_STAGE_BYTES);

    zero_kernel<<<(BB * NN + 255) / 256, 256>>>(out);

    wt_prep_kernel<<<512, 256>>>(Wq, bq, Wk, bk);

    qk_tc_kernel<<<BB * NN / 128, 256, QK_SMEM>>>(hidden, mask);

    stats_kernel<<<BB * NN / 8, 256>>>();
    guard_kernel<<<BB, 256>>>();

    dim3 sgrid(NN / SBN, NN / SBM, BB);   // fallback; early-exits when proven
    score_kernel<<<sgrid, 256, 2 * S_STAGE_BYTES>>>();

    softmax_kernel<<<BB, 256>>>();

    dim3 pgrid(NN / PSEG, BB);   // 32 x 8
    pool_kernel<<<pgrid, 256>>>(hidden, mask, out);
}

// round 9
// speedup vs baseline: 30.3805x; 1.1701x over previous
#include <cuda_runtime.h>
#include <cuda_bf16.h>
#include <math.h>
#include <cstdint>

#define BB 8
#define NN 4096
#define HH 256
#define FF 256

// ---------------------------------------------------------------------------
// Scratch
// ---------------------------------------------------------------------------
__device__ __nv_bfloat16 g_Qh[BB * NN * FF];   // 16 MB
__device__ __nv_bfloat16 g_Kh[BB * NN * FF];   // 16 MB
__device__ float g_T[BB * NN];                 // 128 KB
__device__ __nv_bfloat16 g_WT[512 * HH];       // combined [Wq^T ; Wk^T], [f, h]
__device__ float g_b2[512];                    // combined bias
__device__ float g_Sq[BB * NN], g_Aq[BB * NN]; // row sum, centered sq-norm (Q)
__device__ float g_Sk[BB * NN], g_Ak[BB * NN]; // same for K
__device__ int   g_flag[BB];                   // 1 => all scores saturate

__device__ __forceinline__ float tanh_fast(float x) {
    float y;
    asm("tanh.approx.f32 %0, %1;\n" : "=f"(y) : "f"(x));
    return y;
}
__device__ __forceinline__ float sigmoid_fast(float x) {
    return fmaf(0.5f, tanh_fast(0.5f * x), 0.5f);
}

// ---------------------------------------------------------------------------
// PTX helpers (legacy mma.sync path — tcgen05 unavailable in this toolchain)
// ---------------------------------------------------------------------------
__device__ __forceinline__ void ldsm_x4(unsigned& r0, unsigned& r1, unsigned& r2, unsigned& r3,
                                        unsigned addr) {
    asm volatile("ldmatrix.sync.aligned.m8n8.x4.shared.b16 {%0,%1,%2,%3}, [%4];\n"
                 : "=r"(r0), "=r"(r1), "=r"(r2), "=r"(r3) : "r"(addr));
}
__device__ __forceinline__ void mma16816(float* d, const unsigned* a, unsigned b0, unsigned b1) {
    asm volatile(
        "mma.sync.aligned.m16n8k16.row.col.f32.bf16.bf16.f32 "
        "{%0,%1,%2,%3},{%4,%5,%6,%7},{%8,%9},{%0,%1,%2,%3};\n"
        : "+f"(d[0]), "+f"(d[1]), "+f"(d[2]), "+f"(d[3])
        : "r"(a[0]), "r"(a[1]), "r"(a[2]), "r"(a[3]), "r"(b0), "r"(b1));
}
__device__ __forceinline__ void cp_async16(unsigned dst, const void* src) {
    asm volatile("cp.async.cg.shared.global [%0], [%1], 16;\n" :: "r"(dst), "l"(src));
}
#define CP_COMMIT() asm volatile("cp.async.commit_group;\n" ::: "memory")
#define CP_WAIT1()  asm volatile("cp.async.wait_group 1;\n" ::: "memory")
#define CP_WAIT0()  asm volatile("cp.async.wait_group 0;\n" ::: "memory")

// ---------------------------------------------------------------------------
// Kernel 0: zero T and out
// ---------------------------------------------------------------------------
__global__ void zero_kernel(float* __restrict__ out) {
    int i = blockIdx.x * blockDim.x + threadIdx.x;
    if (i < BB * NN) {
        g_T[i] = 0.0f;
    }
    if (i < BB * HH) out[i] = 0.0f;
}

// ---------------------------------------------------------------------------
// Kernel W: build combined transposed bf16 weights WT[f,h] and bias
// ---------------------------------------------------------------------------
__global__ void wt_prep_kernel(const float* __restrict__ Wq, const float* __restrict__ bq,
                               const float* __restrict__ Wk, const float* __restrict__ bk) {
    int f = blockIdx.x;          // 0..511
    int h = threadIdx.x;         // 0..255
    float w = (f < FF) ? Wq[h * FF + f] : Wk[h * FF + (f - FF)];
    g_WT[f * HH + h] = __float2bfloat16(w);
    if (h == 0) g_b2[f] = (f < FF) ? bq[f] : bk[f - FF];
}

// ---------------------------------------------------------------------------
// Kernel 1: tensor-core QK projection + fused per-row stats.
// C[row, f(0..511)] = sigmoid( (hidden*mask)[row,:] . WT[f,:] + b2[f] )
// Stats (S = sum v, A = sum (v-0.5)^2 over bf16-rounded v) accumulate in
// CTA-local smem, then one direct global store per row.
// NOTE: loadB iterates i<4 (1024 x 16B = full 128-row x 128B tile). The
// earlier i<2 version silently loaded only rows 0..63, leaving rows 64..127
// as stale smem — the source of the intermittent NaNs.
// ---------------------------------------------------------------------------
#define QA_BYTES 65536                 // 128 x 256 bf16 (4 chunk-blocks of 16KB)
#define QB_STAGE 16384                 // 128 x 64 bf16
#define QBIAS_OFF (QA_BYTES + 2 * QB_STAGE)
#define QSTAT_OFF (QBIAS_OFF + 512 * 4)
#define QK_SMEM (QSTAT_OFF + 4 * 128 * 4)   // + sSq/sAq/sSk/sAk[128]

extern __shared__ char s_qk[];

__global__ __launch_bounds__(256, 2) void qk_tc_kernel(const float* __restrict__ hidden,
                                                       const int* __restrict__ mask) {
    const int rowBase = blockIdx.x * 128;
    const int tid = threadIdx.x;
    const int wid = tid >> 5;
    const int lane = tid & 31;
    const int wr = wid >> 1;     // 0..3 : 32-row stripe
    const int wc = wid & 1;      // 0..1 : 64-col stripe
    const uint32_t sb = (uint32_t)__cvta_generic_to_shared(s_qk);
    const uint32_t Asm = sb;
    const uint32_t Bsm = sb + QA_BYTES;
    float* sBias = (float*)(s_qk + QBIAS_OFF);
    float* sStat = (float*)(s_qk + QSTAT_OFF);   // [4][128]: Sq, Aq, Sk, Ak

    sBias[tid] = g_b2[tid];
    sBias[tid + 256] = g_b2[tid + 256];
    if (tid < 128) {
        sStat[tid] = 0.0f; sStat[tid + 128] = 0.0f;
        sStat[tid + 256] = 0.0f; sStat[tid + 384] = 0.0f;
    }

    // ---- load A: hidden*mask -> bf16, swizzled, chunk-blocked ----
    #pragma unroll
    for (int c = 0; c < 4; c++) {
        #pragma unroll
        for (int i = 0; i < 4; i++) {
            int idx = tid + i * 256;
            int r = idx >> 3;
            int cb = idx & 7;
            const float* src = hidden + (size_t)(rowBase + r) * HH + c * 64 + cb * 8;
            float m = (float)mask[rowBase + r];
            float4 f0 = *(const float4*)src;
            float4 f1 = *(const float4*)(src + 4);
            __nv_bfloat162 p0 = __floats2bfloat162_rn(f0.x * m, f0.y * m);
            __nv_bfloat162 p1 = __floats2bfloat162_rn(f0.z * m, f0.w * m);
            __nv_bfloat162 p2 = __floats2bfloat162_rn(f1.x * m, f1.y * m);
            __nv_bfloat162 p3 = __floats2bfloat162_rn(f1.z * m, f1.w * m);
            uint32_t dst = Asm + c * 16384 + r * 128 + ((cb ^ (r & 7)) << 4);
            asm volatile("st.shared.v4.b32 [%0], {%1,%2,%3,%4};\n"
                         :: "r"(dst),
                            "r"(*(uint32_t*)&p0), "r"(*(uint32_t*)&p1),
                            "r"(*(uint32_t*)&p2), "r"(*(uint32_t*)&p3) : "memory");
        }
    }
    __syncthreads();

    // ---- 4 f-tiles of 128 combined output features ----
    for (int ft = 0; ft < 4; ft++) {
        auto loadB = [&](int stage, int c) {
            #pragma unroll
            for (int i = 0; i < 4; i++) {          // FULL tile: 1024 x 16B
                int idx = tid + i * 256;           // 0..1023
                int r = idx >> 3;                  // 0..127 (feature row)
                int cb = idx & 7;
                cp_async16(Bsm + stage * QB_STAGE + r * 128 + ((cb ^ (r & 7)) << 4),
                           g_WT + (size_t)(ft * 128 + r) * HH + c * 64 + cb * 8);
            }
        };

        float acc[2][8][4];
        #pragma unroll
        for (int mi = 0; mi < 2; mi++)
            #pragma unroll
            for (int nf = 0; nf < 8; nf++)
                #pragma unroll
                for (int q = 0; q < 4; q++) acc[mi][nf][q] = 0.0f;

        loadB(0, 0); CP_COMMIT();
        loadB(1, 1); CP_COMMIT();

        #pragma unroll
        for (int c = 0; c < 4; c++) {
            if (c < 3) { CP_WAIT1(); } else { CP_WAIT0(); }
            __syncthreads();

            uint32_t Ab = Asm + c * 16384;
            uint32_t Bb = Bsm + (c & 1) * QB_STAGE;

            #pragma unroll
            for (int kk = 0; kk < 4; kk++) {
                unsigned a[2][4];
                #pragma unroll
                for (int mi = 0; mi < 2; mi++) {
                    int r = wr * 32 + mi * 16 + (lane & 15);
                    int ch = kk * 2 + (lane >> 4);
                    ldsm_x4(a[mi][0], a[mi][1], a[mi][2], a[mi][3],
                            Ab + r * 128 + ((ch ^ (r & 7)) << 4));
                }
                unsigned bv[4][4];
                #pragma unroll
                for (int nb = 0; nb < 4; nb++) {
                    int n = wc * 64 + nb * 16 + (lane & 7) + ((lane >> 4) << 3);
                    int ch = kk * 2 + ((lane >> 3) & 1);
                    ldsm_x4(bv[nb][0], bv[nb][1], bv[nb][2], bv[nb][3],
                            Bb + n * 128 + ((ch ^ (n & 7)) << 4));
                }
                #pragma unroll
                for (int mi = 0; mi < 2; mi++)
                    #pragma unroll
                    for (int nf = 0; nf < 8; nf++)
                        mma16816(acc[mi][nf], a[mi],
                                 bv[nf >> 1][(nf & 1) * 2], bv[nf >> 1][(nf & 1) * 2 + 1]);
            }
            __syncthreads();
            if (c < 2) { loadB(c & 1, c + 2); CP_COMMIT(); }
        }

        // ---- epilogue: bias + sigmoid, store bf16x2, fused stats ----
        const bool isQ = (ft < 2);
        float* sS = isQ ? (sStat)       : (sStat + 256);
        float* sA = isQ ? (sStat + 128) : (sStat + 384);

        #pragma unroll
        for (int mi = 0; mi < 2; mi++) {
            int lrow_lo = wr * 32 + mi * 16 + (lane >> 2);   // local row in [0,128)
            int row_lo = rowBase + lrow_lo;
            int row_hi = row_lo + 8;
            float s_lo = 0.0f, a_lo = 0.0f, s_hi = 0.0f, a_hi = 0.0f;
            #pragma unroll
            for (int nf = 0; nf < 8; nf++) {
                int col = ft * 128 + wc * 64 + nf * 8 + 2 * (lane & 3);
                float b0 = sBias[col], b1 = sBias[col + 1];
                float v00 = sigmoid_fast(acc[mi][nf][0] + b0);
                float v01 = sigmoid_fast(acc[mi][nf][1] + b1);
                float v10 = sigmoid_fast(acc[mi][nf][2] + b0);
                float v11 = sigmoid_fast(acc[mi][nf][3] + b1);
                __nv_bfloat162 plo = __floats2bfloat162_rn(v00, v01);
                __nv_bfloat162 phi = __floats2bfloat162_rn(v10, v11);
                // stats on the bf16-rounded values (what the fallback GEMM sees)
                float r00 = __low2float(plo), r01 = __high2float(plo);
                float r10 = __low2float(phi), r11 = __high2float(phi);
                s_lo += r00 + r01;
                a_lo += (r00 - 0.5f) * (r00 - 0.5f) + (r01 - 0.5f) * (r01 - 0.5f);
                s_hi += r10 + r11;
                a_hi += (r10 - 0.5f) * (r10 - 0.5f) + (r11 - 0.5f) * (r11 - 0.5f);
                if (col < FF) {
                    *(uint32_t*)&g_Qh[(size_t)row_lo * FF + col] = *(uint32_t*)&plo;
                    *(uint32_t*)&g_Qh[(size_t)row_hi * FF + col] = *(uint32_t*)&phi;
                } else {
                    *(uint32_t*)&g_Kh[(size_t)row_lo * FF + col - FF] = *(uint32_t*)&plo;
                    *(uint32_t*)&g_Kh[(size_t)row_hi * FF + col - FF] = *(uint32_t*)&phi;
                }
            }
            // reduce across the 4 lanes sharing each row (lane bits 0-1)
            s_lo += __shfl_xor_sync(0xffffffff, s_lo, 1);
            s_lo += __shfl_xor_sync(0xffffffff, s_lo, 2);
            a_lo += __shfl_xor_sync(0xffffffff, a_lo, 1);
            a_lo += __shfl_xor_sync(0xffffffff, a_lo, 2);
            s_hi += __shfl_xor_sync(0xffffffff, s_hi, 1);
            s_hi += __shfl_xor_sync(0xffffffff, s_hi, 2);
            a_hi += __shfl_xor_sync(0xffffffff, a_hi, 1);
            a_hi += __shfl_xor_sync(0xffffffff, a_hi, 2);
            if ((lane & 3) == 0) {
                atomicAdd(&sS[lrow_lo], s_lo);
                atomicAdd(&sA[lrow_lo], a_lo);
                atomicAdd(&sS[lrow_lo + 8], s_hi);
                atomicAdd(&sA[lrow_lo + 8], a_hi);
            }
        }
    }

    __syncthreads();
    if (tid < 128) {
        int row = rowBase + tid;
        g_Sq[row] = sStat[tid];
        g_Aq[row] = sStat[tid + 128];
        g_Sk[row] = sStat[tid + 256];
        g_Ak[row] = sStat[tid + 384];
    }
}

// ---------------------------------------------------------------------------
// Kernel G: per-batch saturation proof.
// dot(Qn,Km) >= 64 + 0.5(minSq-128) + 0.5(minSk-128) - sqrt(maxAq*maxAk) > 18
// => every off-diag sigmoid == 1.0f exactly (fp32 saturates at ~17.5).
// ---------------------------------------------------------------------------
__global__ __launch_bounds__(256) void guard_kernel() {
    __shared__ float smn[256], smx[256], smn2[256], smx2[256];
    const int b = blockIdx.x;
    const int tid = threadIdx.x;
    float mnSq = 1e30f, mxAq = 0.0f, mnSk = 1e30f, mxAk = 0.0f;
    for (int n = tid; n < NN; n += 256) {
        int i = b * NN + n;
        mnSq = fminf(mnSq, g_Sq[i]); mxAq = fmaxf(mxAq, g_Aq[i]);
        mnSk = fminf(mnSk, g_Sk[i]); mxAk = fmaxf(mxAk, g_Ak[i]);
    }
    smn[tid] = mnSq; smx[tid] = mxAq; smn2[tid] = mnSk; smx2[tid] = mxAk;
    __syncthreads();
    for (int s = 128; s > 0; s >>= 1) {
        if (tid < s) {
            smn[tid] = fminf(smn[tid], smn[tid + s]);
            smx[tid] = fmaxf(smx[tid], smx[tid + s]);
            smn2[tid] = fminf(smn2[tid], smn2[tid + s]);
            smx2[tid] = fmaxf(smx2[tid], smx2[tid + s]);
        }
        __syncthreads();
    }
    if (tid == 0) {
        float bound = 64.0f + 0.5f * (smn[0] - 128.0f) + 0.5f * (smn2[0] - 128.0f)
                    - sqrtf(smx[0]) * sqrtf(smx2[0]);
        g_flag[b] = (bound > 18.0f) ? 1 : 0;
    }
}

// ---------------------------------------------------------------------------
// Kernel 2 (fallback): mma.sync score kernel; early-exits if saturation proven.
// ---------------------------------------------------------------------------
#define SBM 128
#define SBN 128
#define S_STAGE_BYTES 32768

__device__ __forceinline__ float sig_scaled(float x) {
    if (x > 16.0f) return 0.0625f;
    return 0.0625f / (1.0f + __expf(-x));
}

extern __shared__ char s_score[];

__global__ __launch_bounds__(256, 2) void score_kernel() {
    const int b = blockIdx.z;
    if (g_flag[b]) return;

    const int rowBase = blockIdx.y * SBM;
    const int colBase = blockIdx.x * SBN;
    const __nv_bfloat16* __restrict__ Qb = g_Qh + (size_t)b * NN * FF;
    const __nv_bfloat16* __restrict__ Kb = g_Kh + (size_t)b * NN * FF;

    const int tid = threadIdx.x;
    const int wid = tid >> 5;
    const int lane = tid & 31;
    const int wr = wid >> 1;
    const int wc = wid & 1;

    unsigned sbase = (unsigned)__cvta_generic_to_shared(s_score);

    float acc[2][8][4];
    #pragma unroll
    for (int mi = 0; mi < 2; mi++)
        #pragma unroll
        for (int nf = 0; nf < 8; nf++)
            #pragma unroll
            for (int q = 0; q < 4; q++) acc[mi][nf][q] = 0.0f;

    auto load_tile = [&](int stage, int k0) {
        unsigned Ab = sbase + stage * S_STAGE_BYTES;
        unsigned Bb = Ab + 16384;
        #pragma unroll
        for (int i = 0; i < 4; i++) {
            int idx = tid + i * 256;
            int r = idx >> 3;
            int cb = idx & 7;
            unsigned off = r * 128 + ((cb ^ (r & 7)) << 4);
            cp_async16(Ab + off, Qb + (size_t)(rowBase + r) * FF + k0 + cb * 8);
            cp_async16(Bb + off, Kb + (size_t)(colBase + r) * FF + k0 + cb * 8);
        }
    };

    load_tile(0, 0);
    CP_COMMIT();

    const int NSTEP = FF / 64;
    for (int ks = 0; ks < NSTEP; ks++) {
        if (ks + 1 < NSTEP) load_tile((ks + 1) & 1, (ks + 1) * 64);
        CP_COMMIT();
        CP_WAIT1();
        __syncthreads();

        unsigned Ab = sbase + (ks & 1) * S_STAGE_BYTES;
        unsigned Bb = Ab + 16384;

        #pragma unroll
        for (int kk = 0; kk < 4; kk++) {
            unsigned a[2][4];
            #pragma unroll
            for (int mi = 0; mi < 2; mi++) {
                int r = wr * 32 + mi * 16 + (lane & 15);
                int ch = kk * 2 + (lane >> 4);
                ldsm_x4(a[mi][0], a[mi][1], a[mi][2], a[mi][3],
                        Ab + r * 128 + ((ch ^ (r & 7)) << 4));
            }
            unsigned bv[4][4];
            #pragma unroll
            for (int nb = 0; nb < 4; nb++) {
                int n = wc * 64 + nb * 16 + (lane & 7) + ((lane >> 4) << 3);
                int ch = kk * 2 + ((lane >> 3) & 1);
                ldsm_x4(bv[nb][0], bv[nb][1], bv[nb][2], bv[nb][3],
                        Bb + n * 128 + ((ch ^ (n & 7)) << 4));
            }
            #pragma unroll
            for (int mi = 0; mi < 2; mi++)
                #pragma unroll
                for (int nf = 0; nf < 8; nf++)
                    mma16816(acc[mi][nf], a[mi],
                             bv[nf >> 1][(nf & 1) * 2], bv[nf >> 1][(nf & 1) * 2 + 1]);
        }
        __syncthreads();
    }

    float* red = (float*)s_score;

    #pragma unroll
    for (int mi = 0; mi < 2; mi++) {
        int lrow_lo = wr * 32 + mi * 16 + (lane >> 2);
        int lrow_hi = lrow_lo + 8;
        int grow_lo = rowBase + lrow_lo;
        int grow_hi = rowBase + lrow_hi;
        float slo = 0.0f, shi = 0.0f;
        #pragma unroll
        for (int nf = 0; nf < 8; nf++) {
            int col0 = colBase + wc * 64 + nf * 8 + 2 * (lane & 3);
            int col1 = col0 + 1;
            float v;
            v = sig_scaled(acc[mi][nf][0]); if (grow_lo != col0) slo += v;
            v = sig_scaled(acc[mi][nf][1]); if (grow_lo != col1) slo += v;
            v = sig_scaled(acc[mi][nf][2]); if (grow_hi != col0) shi += v;
            v = sig_scaled(acc[mi][nf][3]); if (grow_hi != col1) shi += v;
        }
        slo += __shfl_xor_sync(0xffffffff, slo, 1);
        slo += __shfl_xor_sync(0xffffffff, slo, 2);
        shi += __shfl_xor_sync(0xffffffff, shi, 1);
        shi += __shfl_xor_sync(0xffffffff, shi, 2);
        if ((lane & 3) == 0) {
            red[(lrow_lo << 1) | wc] = slo;
            red[(lrow_hi << 1) | wc] = shi;
        }
    }
    __syncthreads();
    if (tid < SBM) {
        atomicAdd(&g_T[b * NN + rowBase + tid], red[tid * 2] + red[tid * 2 + 1]);
    }
}

// ---------------------------------------------------------------------------
// Kernel 3: softmax over T rows. Skipped for proven-saturated batches
// (pool then uses the exact uniform weight 1/4096 = softmax of constant T).
// ---------------------------------------------------------------------------
__global__ void softmax_kernel() {
    __shared__ float sred[256];
    const int b = blockIdx.x;
    if (g_flag[b]) return;
    const int tid = threadIdx.x;
    float* T = g_T + b * NN;

    float mx = -1e30f;
    for (int n = tid; n < NN; n += 256) mx = fmaxf(mx, T[n]);
    sred[tid] = mx;
    __syncthreads();
    for (int s = 128; s > 0; s >>= 1) {
        if (tid < s) sred[tid] = fmaxf(sred[tid], sred[tid + s]);
        __syncthreads();
    }
    mx = sred[0];
    __syncthreads();

    float sum = 0.0f;
    for (int n = tid; n < NN; n += 256) {
        float e = __expf(T[n] - mx);
        T[n] = e;
        sum += e;
    }
    sred[tid] = sum;
    __syncthreads();
    for (int s = 128; s > 0; s >>= 1) {
        if (tid < s) sred[tid] += sred[tid + s];
        __syncthreads();
    }
    const float inv = 1.0f / sred[0];
    __syncthreads();
    for (int n = tid; n < NN; n += 256) T[n] *= inv;
}

// ---------------------------------------------------------------------------
// Kernel 4: out[b,h] = sum_n w[b,n] * mask[b,n] * hidden[b,n,h]
// w = 1/4096 exactly (saturated case) or softmaxed T (fallback case).
// ---------------------------------------------------------------------------
#define PSEG 128
__global__ __launch_bounds__(256) void pool_kernel(const float* __restrict__ hidden,
                            const int*   __restrict__ mask,
                            float* __restrict__ out) {
    __shared__ float t[PSEG];
    const int b = blockIdx.y;
    const int n0 = blockIdx.x * PSEG;
    const int tid = threadIdx.x;
    const int flag = g_flag[b];

    if (tid < PSEG) {
        int gn = b * NN + n0 + tid;
        float w = flag ? 2.44140625e-4f : g_T[gn];   // 1/4096 exact
        t[tid] = w * (float)mask[gn];
    }
    __syncthreads();

    float acc = 0.0f;
    const float* hb = hidden + ((size_t)b * NN + n0) * HH + tid;
    #pragma unroll 8
    for (int n = 0; n < PSEG; n++)
        acc = fmaf(t[n], hb[(size_t)n * HH], acc);

    atomicAdd(&out[b * HH + tid], acc);
}

// ---------------------------------------------------------------------------
// Launch
// ---------------------------------------------------------------------------
extern "C" void kernel_launch(void* const* d_in, const int* in_sizes, int n_in,
                              void* d_out, int out_size) {
    const float* hidden = (const float*)d_in[0];
    const int*   mask   = (const int*)  d_in[1];
    const float* Wq     = (const float*)d_in[2];
    const float* bq     = (const float*)d_in[3];
    const float* Wk     = (const float*)d_in[4];
    const float* bk     = (const float*)d_in[5];
    float* out = (float*)d_out;

    cudaFuncSetAttribute(qk_tc_kernel,
                         cudaFuncAttributeMaxDynamicSharedMemorySize, QK_SMEM);
    cudaFuncSetAttribute(score_kernel,
                         cudaFuncAttributeMaxDynamicSharedMemorySize, 2 * S_STAGE_BYTES);

    zero_kernel<<<(BB * NN + 255) / 256, 256>>>(out);

    wt_prep_kernel<<<512, 256>>>(Wq, bq, Wk, bk);

    qk_tc_kernel<<<BB * NN / 128, 256, QK_SMEM>>>(hidden, mask);

    guard_kernel<<<BB, 256>>>();

    dim3 sgrid(NN / SBN, NN / SBM, BB);   // fallback; early-exits when proven
    score_kernel<<<sgrid, 256, 2 * S_STAGE_BYTES>>>();

    softmax_kernel<<<BB, 256>>>();

    dim3 pgrid(NN / PSEG, BB);   // 32 x 8
    pool_kernel<<<pgrid, 256>>>(hidden, mask, out);
}

// round 10
// speedup vs baseline: 36.0980x; 1.1882x over previous
#include <cuda_runtime.h>
#include <cuda_bf16.h>
#include <math.h>
#include <cstdint>

#define BB 8
#define NN 4096
#define HH 256
#define FF 256

// ---------------------------------------------------------------------------
// Scratch
// ---------------------------------------------------------------------------
__device__ __nv_bfloat16 g_Qh[BB * NN * FF];   // 16 MB (fallback only)
__device__ __nv_bfloat16 g_Kh[BB * NN * FF];   // 16 MB (fallback only)
__device__ float g_T[BB * NN];                 // 128 KB
__device__ __nv_bfloat16 g_WT[512 * HH];       // combined [Wq^T ; Wk^T], [f, h]
__device__ float g_b2[512];                    // combined bias
__device__ float4 g_cagg[256];                 // per-CTA {minSq, maxAq, minSk, maxAk}
__device__ int   g_flag[BB];                   // 1 => all scores saturate

__device__ __forceinline__ float tanh_fast(float x) {
    float y;
    asm("tanh.approx.f32 %0, %1;\n" : "=f"(y) : "f"(x));
    return y;
}
__device__ __forceinline__ float sigmoid_fast(float x) {
    return fmaf(0.5f, tanh_fast(0.5f * x), 0.5f);
}

// ---------------------------------------------------------------------------
// PTX helpers (legacy mma.sync path — tcgen05 unavailable in this toolchain)
// ---------------------------------------------------------------------------
__device__ __forceinline__ void ldsm_x4(unsigned& r0, unsigned& r1, unsigned& r2, unsigned& r3,
                                        unsigned addr) {
    asm volatile("ldmatrix.sync.aligned.m8n8.x4.shared.b16 {%0,%1,%2,%3}, [%4];\n"
                 : "=r"(r0), "=r"(r1), "=r"(r2), "=r"(r3) : "r"(addr));
}
__device__ __forceinline__ void mma16816(float* d, const unsigned* a, unsigned b0, unsigned b1) {
    asm volatile(
        "mma.sync.aligned.m16n8k16.row.col.f32.bf16.bf16.f32 "
        "{%0,%1,%2,%3},{%4,%5,%6,%7},{%8,%9},{%0,%1,%2,%3};\n"
        : "+f"(d[0]), "+f"(d[1]), "+f"(d[2]), "+f"(d[3])
        : "r"(a[0]), "r"(a[1]), "r"(a[2]), "r"(a[3]), "r"(b0), "r"(b1));
}
__device__ __forceinline__ void cp_async16(unsigned dst, const void* src) {
    asm volatile("cp.async.cg.shared.global [%0], [%1], 16;\n" :: "r"(dst), "l"(src));
}
#define CP_COMMIT() asm volatile("cp.async.commit_group;\n" ::: "memory")
#define CP_WAIT1()  asm volatile("cp.async.wait_group 1;\n" ::: "memory")
#define CP_WAIT0()  asm volatile("cp.async.wait_group 0;\n" ::: "memory")

// ---------------------------------------------------------------------------
// Kernel W: build combined transposed bf16 weights + bias; zero T and out.
// grid 512 x 256 threads (131072 threads >= BB*NN).
// ---------------------------------------------------------------------------
__global__ void wt_prep_kernel(const float* __restrict__ Wq, const float* __restrict__ bq,
                               const float* __restrict__ Wk, const float* __restrict__ bk,
                               float* __restrict__ out) {
    int f = blockIdx.x;          // 0..511
    int h = threadIdx.x;         // 0..255
    float w = (f < FF) ? Wq[h * FF + f] : Wk[h * FF + (f - FF)];
    g_WT[f * HH + h] = __float2bfloat16(w);
    if (h == 0) g_b2[f] = (f < FF) ? bq[f] : bk[f - FF];

    int i = f * 256 + h;
    if (i < BB * NN) g_T[i] = 0.0f;
    if (i < BB * HH) out[i] = 0.0f;
}

// ---------------------------------------------------------------------------
// Kernel 1 (templated): tensor-core QK projection.
// DO_STATS: per-row stats in CTA smem -> CTA-level {minS, maxA} aggregates.
// STORE_QK: write Q/K to global (fallback-only pass; flag-gated early exit).
// loadB iterates i<4: FULL 128-row x 128B tile (the i<2 half-load was the
// round-5/8 NaN source).
// ---------------------------------------------------------------------------
#define QA_BYTES 65536                 // 128 x 256 bf16 (4 chunk-blocks of 16KB)
#define QB_STAGE 16384                 // 128 x 64 bf16
#define QBIAS_OFF (QA_BYTES + 2 * QB_STAGE)
#define QSTAT_OFF (QBIAS_OFF + 512 * 4)
#define QK_SMEM (QSTAT_OFF + (4 * 128 + 16) * 4)   // stats[512] + partials[16]

extern __shared__ char s_qk[];

template<bool STORE_QK, bool DO_STATS>
__global__ __launch_bounds__(256, 2) void qk_tc_kernel_t(const float* __restrict__ hidden,
                                                         const int* __restrict__ mask) {
    const int rowBase = blockIdx.x * 128;
    if (STORE_QK) {
        if (g_flag[blockIdx.x >> 5]) return;   // 32 CTAs per batch
    }
    const int tid = threadIdx.x;
    const int wid = tid >> 5;
    const int lane = tid & 31;
    const int wr = wid >> 1;     // 0..3 : 32-row stripe
    const int wc = wid & 1;      // 0..1 : 64-col stripe
    const uint32_t sb = (uint32_t)__cvta_generic_to_shared(s_qk);
    const uint32_t Asm = sb;
    const uint32_t Bsm = sb + QA_BYTES;
    float* sBias = (float*)(s_qk + QBIAS_OFF);
    float* sStat = (float*)(s_qk + QSTAT_OFF);   // [4][128] + 16 partials

    sBias[tid] = g_b2[tid];
    sBias[tid + 256] = g_b2[tid + 256];
    if (DO_STATS && tid < 128) {
        sStat[tid] = 0.0f; sStat[tid + 128] = 0.0f;
        sStat[tid + 256] = 0.0f; sStat[tid + 384] = 0.0f;
    }

    // ---- load A: hidden*mask -> bf16, swizzled, chunk-blocked ----
    #pragma unroll
    for (int c = 0; c < 4; c++) {
        #pragma unroll
        for (int i = 0; i < 4; i++) {
            int idx = tid + i * 256;
            int r = idx >> 3;
            int cb = idx & 7;
            const float* src = hidden + (size_t)(rowBase + r) * HH + c * 64 + cb * 8;
            float m = (float)mask[rowBase + r];
            float4 f0 = *(const float4*)src;
            float4 f1 = *(const float4*)(src + 4);
            __nv_bfloat162 p0 = __floats2bfloat162_rn(f0.x * m, f0.y * m);
            __nv_bfloat162 p1 = __floats2bfloat162_rn(f0.z * m, f0.w * m);
            __nv_bfloat162 p2 = __floats2bfloat162_rn(f1.x * m, f1.y * m);
            __nv_bfloat162 p3 = __floats2bfloat162_rn(f1.z * m, f1.w * m);
            uint32_t dst = Asm + c * 16384 + r * 128 + ((cb ^ (r & 7)) << 4);
            asm volatile("st.shared.v4.b32 [%0], {%1,%2,%3,%4};\n"
                         :: "r"(dst),
                            "r"(*(uint32_t*)&p0), "r"(*(uint32_t*)&p1),
                            "r"(*(uint32_t*)&p2), "r"(*(uint32_t*)&p3) : "memory");
        }
    }
    __syncthreads();

    // ---- 4 f-tiles of 128 combined output features ----
    for (int ft = 0; ft < 4; ft++) {
        auto loadB = [&](int stage, int c) {
            #pragma unroll
            for (int i = 0; i < 4; i++) {          // FULL tile: 1024 x 16B
                int idx = tid + i * 256;           // 0..1023
                int r = idx >> 3;                  // 0..127 (feature row)
                int cb = idx & 7;
                cp_async16(Bsm + stage * QB_STAGE + r * 128 + ((cb ^ (r & 7)) << 4),
                           g_WT + (size_t)(ft * 128 + r) * HH + c * 64 + cb * 8);
            }
        };

        float acc[2][8][4];
        #pragma unroll
        for (int mi = 0; mi < 2; mi++)
            #pragma unroll
            for (int nf = 0; nf < 8; nf++)
                #pragma unroll
                for (int q = 0; q < 4; q++) acc[mi][nf][q] = 0.0f;

        loadB(0, 0); CP_COMMIT();
        loadB(1, 1); CP_COMMIT();

        #pragma unroll
        for (int c = 0; c < 4; c++) {
            if (c < 3) { CP_WAIT1(); } else { CP_WAIT0(); }
            __syncthreads();

            uint32_t Ab = Asm + c * 16384;
            uint32_t Bb = Bsm + (c & 1) * QB_STAGE;

            #pragma unroll
            for (int kk = 0; kk < 4; kk++) {
                unsigned a[2][4];
                #pragma unroll
                for (int mi = 0; mi < 2; mi++) {
                    int r = wr * 32 + mi * 16 + (lane & 15);
                    int ch = kk * 2 + (lane >> 4);
                    ldsm_x4(a[mi][0], a[mi][1], a[mi][2], a[mi][3],
                            Ab + r * 128 + ((ch ^ (r & 7)) << 4));
                }
                unsigned bv[4][4];
                #pragma unroll
                for (int nb = 0; nb < 4; nb++) {
                    int n = wc * 64 + nb * 16 + (lane & 7) + ((lane >> 4) << 3);
                    int ch = kk * 2 + ((lane >> 3) & 1);
                    ldsm_x4(bv[nb][0], bv[nb][1], bv[nb][2], bv[nb][3],
                            Bb + n * 128 + ((ch ^ (n & 7)) << 4));
                }
                #pragma unroll
                for (int mi = 0; mi < 2; mi++)
                    #pragma unroll
                    for (int nf = 0; nf < 8; nf++)
                        mma16816(acc[mi][nf], a[mi],
                                 bv[nf >> 1][(nf & 1) * 2], bv[nf >> 1][(nf & 1) * 2 + 1]);
            }
            __syncthreads();
            if (c < 2) { loadB(c & 1, c + 2); CP_COMMIT(); }
        }

        // ---- epilogue: bias + sigmoid; stats and/or stores ----
        const bool isQ = (ft < 2);
        float* sS = isQ ? (sStat)       : (sStat + 256);
        float* sA = isQ ? (sStat + 128) : (sStat + 384);

        #pragma unroll
        for (int mi = 0; mi < 2; mi++) {
            int lrow_lo = wr * 32 + mi * 16 + (lane >> 2);   // local row in [0,128)
            int row_lo = rowBase + lrow_lo;
            int row_hi = row_lo + 8;
            float s_lo = 0.0f, a_lo = 0.0f, s_hi = 0.0f, a_hi = 0.0f;
            #pragma unroll
            for (int nf = 0; nf < 8; nf++) {
                int col = ft * 128 + wc * 64 + nf * 8 + 2 * (lane & 3);
                float b0 = sBias[col], b1 = sBias[col + 1];
                float v00 = sigmoid_fast(acc[mi][nf][0] + b0);
                float v01 = sigmoid_fast(acc[mi][nf][1] + b1);
                float v10 = sigmoid_fast(acc[mi][nf][2] + b0);
                float v11 = sigmoid_fast(acc[mi][nf][3] + b1);
                __nv_bfloat162 plo = __floats2bfloat162_rn(v00, v01);
                __nv_bfloat162 phi = __floats2bfloat162_rn(v10, v11);
                if (DO_STATS) {
                    // stats on bf16-rounded values (what the fallback GEMM sees)
                    float r00 = __low2float(plo), r01 = __high2float(plo);
                    float r10 = __low2float(phi), r11 = __high2float(phi);
                    s_lo += r00 + r01;
                    a_lo += (r00 - 0.5f) * (r00 - 0.5f) + (r01 - 0.5f) * (r01 - 0.5f);
                    s_hi += r10 + r11;
                    a_hi += (r10 - 0.5f) * (r10 - 0.5f) + (r11 - 0.5f) * (r11 - 0.5f);
                }
                if (STORE_QK) {
                    if (col < FF) {
                        *(uint32_t*)&g_Qh[(size_t)row_lo * FF + col] = *(uint32_t*)&plo;
                        *(uint32_t*)&g_Qh[(size_t)row_hi * FF + col] = *(uint32_t*)&phi;
                    } else {
                        *(uint32_t*)&g_Kh[(size_t)row_lo * FF + col - FF] = *(uint32_t*)&plo;
                        *(uint32_t*)&g_Kh[(size_t)row_hi * FF + col - FF] = *(uint32_t*)&phi;
                    }
                }
            }
            if (DO_STATS) {
                s_lo += __shfl_xor_sync(0xffffffff, s_lo, 1);
                s_lo += __shfl_xor_sync(0xffffffff, s_lo, 2);
                a_lo += __shfl_xor_sync(0xffffffff, a_lo, 1);
                a_lo += __shfl_xor_sync(0xffffffff, a_lo, 2);
                s_hi += __shfl_xor_sync(0xffffffff, s_hi, 1);
                s_hi += __shfl_xor_sync(0xffffffff, s_hi, 2);
                a_hi += __shfl_xor_sync(0xffffffff, a_hi, 1);
                a_hi += __shfl_xor_sync(0xffffffff, a_hi, 2);
                if ((lane & 3) == 0) {
                    atomicAdd(&sS[lrow_lo], s_lo);
                    atomicAdd(&sA[lrow_lo], a_lo);
                    atomicAdd(&sS[lrow_lo + 8], s_hi);
                    atomicAdd(&sA[lrow_lo + 8], a_hi);
                }
            }
        }
    }

    // ---- CTA-level aggregate: {min Sq, max Aq, min Sk, max Ak} ----
    if (DO_STATS) {
        __syncthreads();
        float* sPart = sStat + 512;   // 16 partial slots (separate from rows)
        if (tid < 128) {
            float s_q = sStat[tid],       a_q = sStat[tid + 128];
            float s_k = sStat[tid + 256], a_k = sStat[tid + 384];
            #pragma unroll
            for (int o = 16; o > 0; o >>= 1) {
                s_q = fminf(s_q, __shfl_xor_sync(0xffffffff, s_q, o));
                a_q = fmaxf(a_q, __shfl_xor_sync(0xffffffff, a_q, o));
                s_k = fminf(s_k, __shfl_xor_sync(0xffffffff, s_k, o));
                a_k = fmaxf(a_k, __shfl_xor_sync(0xffffffff, a_k, o));
            }
            if (lane == 0) {
                int w = tid >> 5;   // 0..3
                sPart[w] = s_q; sPart[4 + w] = a_q;
                sPart[8 + w] = s_k; sPart[12 + w] = a_k;
            }
        }
        __syncthreads();
        if (tid == 0) {
            float mnq = fminf(fminf(sPart[0], sPart[1]), fminf(sPart[2], sPart[3]));
            float mxq = fmaxf(fmaxf(sPart[4], sPart[5]), fmaxf(sPart[6], sPart[7]));
            float mnk = fminf(fminf(sPart[8], sPart[9]), fminf(sPart[10], sPart[11]));
            float mxk = fmaxf(fmaxf(sPart[12], sPart[13]), fmaxf(sPart[14], sPart[15]));
            g_cagg[blockIdx.x] = make_float4(mnq, mxq, mnk, mxk);
        }
    }
}

// ---------------------------------------------------------------------------
// Kernel G: per-batch saturation proof from CTA aggregates (32 per batch).
// dot(Qn,Km) >= 64 + 0.5(minSq-128) + 0.5(minSk-128) - sqrt(maxAq*maxAk) > 18
// => every off-diag sigmoid == 1.0f exactly (fp32 saturates at ~17.5).
// ---------------------------------------------------------------------------
__global__ void guard_kernel() {
    const int b = blockIdx.x;
    const int lane = threadIdx.x;   // 32 threads
    float4 v = g_cagg[b * 32 + lane];
    float mnq = v.x, mxq = v.y, mnk = v.z, mxk = v.w;
    #pragma unroll
    for (int o = 16; o > 0; o >>= 1) {
        mnq = fminf(mnq, __shfl_xor_sync(0xffffffff, mnq, o));
        mxq = fmaxf(mxq, __shfl_xor_sync(0xffffffff, mxq, o));
        mnk = fminf(mnk, __shfl_xor_sync(0xffffffff, mnk, o));
        mxk = fmaxf(mxk, __shfl_xor_sync(0xffffffff, mxk, o));
    }
    if (lane == 0) {
        float bound = 64.0f + 0.5f * (mnq - 128.0f) + 0.5f * (mnk - 128.0f)
                    - sqrtf(mxq) * sqrtf(mxk);
        g_flag[b] = (bound > 18.0f) ? 1 : 0;
    }
}

// ---------------------------------------------------------------------------
// Kernel 2 (fallback): mma.sync score kernel; early-exits if saturation proven.
// ---------------------------------------------------------------------------
#define SBM 128
#define SBN 128
#define S_STAGE_BYTES 32768

__device__ __forceinline__ float sig_scaled(float x) {
    if (x > 16.0f) return 0.0625f;
    return 0.0625f / (1.0f + __expf(-x));
}

extern __shared__ char s_score[];

__global__ __launch_bounds__(256, 2) void score_kernel() {
    const int b = blockIdx.z;
    if (g_flag[b]) return;

    const int rowBase = blockIdx.y * SBM;
    const int colBase = blockIdx.x * SBN;
    const __nv_bfloat16* __restrict__ Qb = g_Qh + (size_t)b * NN * FF;
    const __nv_bfloat16* __restrict__ Kb = g_Kh + (size_t)b * NN * FF;

    const int tid = threadIdx.x;
    const int wid = tid >> 5;
    const int lane = tid & 31;
    const int wr = wid >> 1;
    const int wc = wid & 1;

    unsigned sbase = (unsigned)__cvta_generic_to_shared(s_score);

    float acc[2][8][4];
    #pragma unroll
    for (int mi = 0; mi < 2; mi++)
        #pragma unroll
        for (int nf = 0; nf < 8; nf++)
            #pragma unroll
            for (int q = 0; q < 4; q++) acc[mi][nf][q] = 0.0f;

    auto load_tile = [&](int stage, int k0) {
        unsigned Ab = sbase + stage * S_STAGE_BYTES;
        unsigned Bb = Ab + 16384;
        #pragma unroll
        for (int i = 0; i < 4; i++) {
            int idx = tid + i * 256;
            int r = idx >> 3;
            int cb = idx & 7;
            unsigned off = r * 128 + ((cb ^ (r & 7)) << 4);
            cp_async16(Ab + off, Qb + (size_t)(rowBase + r) * FF + k0 + cb * 8);
            cp_async16(Bb + off, Kb + (size_t)(colBase + r) * FF + k0 + cb * 8);
        }
    };

    load_tile(0, 0);
    CP_COMMIT();

    const int NSTEP = FF / 64;
    for (int ks = 0; ks < NSTEP; ks++) {
        if (ks + 1 < NSTEP) load_tile((ks + 1) & 1, (ks + 1) * 64);
        CP_COMMIT();
        CP_WAIT1();
        __syncthreads();

        unsigned Ab = sbase + (ks & 1) * S_STAGE_BYTES;
        unsigned Bb = Ab + 16384;

        #pragma unroll
        for (int kk = 0; kk < 4; kk++) {
            unsigned a[2][4];
            #pragma unroll
            for (int mi = 0; mi < 2; mi++) {
                int r = wr * 32 + mi * 16 + (lane & 15);
                int ch = kk * 2 + (lane >> 4);
                ldsm_x4(a[mi][0], a[mi][1], a[mi][2], a[mi][3],
                        Ab + r * 128 + ((ch ^ (r & 7)) << 4));
            }
            unsigned bv[4][4];
            #pragma unroll
            for (int nb = 0; nb < 4; nb++) {
                int n = wc * 64 + nb * 16 + (lane & 7) + ((lane >> 4) << 3);
                int ch = kk * 2 + ((lane >> 3) & 1);
                ldsm_x4(bv[nb][0], bv[nb][1], bv[nb][2], bv[nb][3],
                        Bb + n * 128 + ((ch ^ (n & 7)) << 4));
            }
            #pragma unroll
            for (int mi = 0; mi < 2; mi++)
                #pragma unroll
                for (int nf = 0; nf < 8; nf++)
                    mma16816(acc[mi][nf], a[mi],
                             bv[nf >> 1][(nf & 1) * 2], bv[nf >> 1][(nf & 1) * 2 + 1]);
        }
        __syncthreads();
    }

    float* red = (float*)s_score;

    #pragma unroll
    for (int mi = 0; mi < 2; mi++) {
        int lrow_lo = wr * 32 + mi * 16 + (lane >> 2);
        int lrow_hi = lrow_lo + 8;
        int grow_lo = rowBase + lrow_lo;
        int grow_hi = rowBase + lrow_hi;
        float slo = 0.0f, shi = 0.0f;
        #pragma unroll
        for (int nf = 0; nf < 8; nf++) {
            int col0 = colBase + wc * 64 + nf * 8 + 2 * (lane & 3);
            int col1 = col0 + 1;
            float v;
            v = sig_scaled(acc[mi][nf][0]); if (grow_lo != col0) slo += v;
            v = sig_scaled(acc[mi][nf][1]); if (grow_lo != col1) slo += v;
            v = sig_scaled(acc[mi][nf][2]); if (grow_hi != col0) shi += v;
            v = sig_scaled(acc[mi][nf][3]); if (grow_hi != col1) shi += v;
        }
        slo += __shfl_xor_sync(0xffffffff, slo, 1);
        slo += __shfl_xor_sync(0xffffffff, slo, 2);
        shi += __shfl_xor_sync(0xffffffff, shi, 1);
        shi += __shfl_xor_sync(0xffffffff, shi, 2);
        if ((lane & 3) == 0) {
            red[(lrow_lo << 1) | wc] = slo;
            red[(lrow_hi << 1) | wc] = shi;
        }
    }
    __syncthreads();
    if (tid < SBM) {
        atomicAdd(&g_T[b * NN + rowBase + tid], red[tid * 2] + red[tid * 2 + 1]);
    }
}

// ---------------------------------------------------------------------------
// Kernel 3: softmax over T rows. Skipped for proven-saturated batches
// (pool then uses the exact uniform weight 1/4096 = softmax of constant T).
// ---------------------------------------------------------------------------
__global__ void softmax_kernel() {
    __shared__ float sred[256];
    const int b = blockIdx.x;
    if (g_flag[b]) return;
    const int tid = threadIdx.x;
    float* T = g_T + b * NN;

    float mx = -1e30f;
    for (int n = tid; n < NN; n += 256) mx = fmaxf(mx, T[n]);
    sred[tid] = mx;
    __syncthreads();
    for (int s = 128; s > 0; s >>= 1) {
        if (tid < s) sred[tid] = fmaxf(sred[tid], sred[tid + s]);
        __syncthreads();
    }
    mx = sred[0];
    __syncthreads();

    float sum = 0.0f;
    for (int n = tid; n < NN; n += 256) {
        float e = __expf(T[n] - mx);
        T[n] = e;
        sum += e;
    }
    sred[tid] = sum;
    __syncthreads();
    for (int s = 128; s > 0; s >>= 1) {
        if (tid < s) sred[tid] += sred[tid + s];
        __syncthreads();
    }
    const float inv = 1.0f / sred[0];
    __syncthreads();
    for (int n = tid; n < NN; n += 256) T[n] *= inv;
}

// ---------------------------------------------------------------------------
// Kernel 4: out[b,h] = sum_n w[b,n] * mask[b,n] * hidden[b,n,h]
// w = 1/4096 exactly (saturated case) or softmaxed T (fallback case).
// ---------------------------------------------------------------------------
#define PSEG 128
__global__ __launch_bounds__(256) void pool_kernel(const float* __restrict__ hidden,
                            const int*   __restrict__ mask,
                            float* __restrict__ out) {
    __shared__ float t[PSEG];
    const int b = blockIdx.y;
    const int n0 = blockIdx.x * PSEG;
    const int tid = threadIdx.x;
    const int flag = g_flag[b];

    if (tid < PSEG) {
        int gn = b * NN + n0 + tid;
        float w = flag ? 2.44140625e-4f : g_T[gn];   // 1/4096 exact
        t[tid] = w * (float)mask[gn];
    }
    __syncthreads();

    float acc = 0.0f;
    const float* hb = hidden + ((size_t)b * NN + n0) * HH + tid;
    #pragma unroll 8
    for (int n = 0; n < PSEG; n++)
        acc = fmaf(t[n], hb[(size_t)n * HH], acc);

    atomicAdd(&out[b * HH + tid], acc);
}

// ---------------------------------------------------------------------------
// Launch
// ---------------------------------------------------------------------------
extern "C" void kernel_launch(void* const* d_in, const int* in_sizes, int n_in,
                              void* d_out, int out_size) {
    const float* hidden = (const float*)d_in[0];
    const int*   mask   = (const int*)  d_in[1];
    const float* Wq     = (const float*)d_in[2];
    const float* bq     = (const float*)d_in[3];
    const float* Wk     = (const float*)d_in[4];
    const float* bk     = (const float*)d_in[5];
    float* out = (float*)d_out;

    cudaFuncSetAttribute(qk_tc_kernel_t<false, true>,
                         cudaFuncAttributeMaxDynamicSharedMemorySize, QK_SMEM);
    cudaFuncSetAttribute(qk_tc_kernel_t<true, false>,
                         cudaFuncAttributeMaxDynamicSharedMemorySize, QK_SMEM);
    cudaFuncSetAttribute(score_kernel,
                         cudaFuncAttributeMaxDynamicSharedMemorySize, 2 * S_STAGE_BYTES);

    wt_prep_kernel<<<512, 256>>>(Wq, bq, Wk, bk, out);

    // compute pass: stats only, no Q/K global stores
    qk_tc_kernel_t<false, true><<<BB * NN / 128, 256, QK_SMEM>>>(hidden, mask);

    guard_kernel<<<BB, 32>>>();

    // store pass: only materializes Q/K if the proof failed for that batch
    qk_tc_kernel_t<true, false><<<BB * NN / 128, 256, QK_SMEM>>>(hidden, mask);

    dim3 sgrid(NN / SBN, NN / SBM, BB);   // fallback; early-exits when proven
    score_kernel<<<sgrid, 256, 2 * S_STAGE_BYTES>>>();

    softmax_kernel<<<BB, 256>>>();

    dim3 pgrid(NN / PSEG, BB);   // 32 x 8
    pool_kernel<<<pgrid, 256>>>(hidden, mask, out);
}